// round 14
// baseline (speedup 1.0000x reference)
#include <cuda_runtime.h>
#include <cuda_bf16.h>
#include <math.h>
#include <stdint.h>

// Problem constants
#define Lc 12
#define Hc 768
#define NHc 12
#define DHc 64
#define FFc 3072
#define Vc 21128
#define Sc 512
#define Bc 8
#define Mc (Bc*Sc)          // 4096 tokens
#define SEPc 102
#define LN_EPS 1e-12f
#define QKVN 2304
#define NTILES 166          // ceil(Vc/128)

typedef __nv_bfloat16 bf16;
typedef __nv_bfloat162 bf162;

// ---------------- Device scratch (static; no runtime allocation) ----------------
__device__ float g_x[Mc*Hc];               // fp32 residual stream
__device__ bf16  g_xb[Mc*Hc];              // bf16 copy of x (GEMM A operand)
__device__ bf16  g_qkvb[(size_t)Mc*QKVN];  // fused QKV output (bf16)
__device__ bf16  g_ctxb[Mc*Hc];            // attention output (bf16, feeds Wo)
__device__ float g_proj[Mc*Hc];            // fp32 GEMM output before residual+LN
__device__ bf16  g_ffnb[(size_t)Mc*FFc];   // GELU output (bf16, feeds Wd)
__device__ float g_pmax[(size_t)Mc*NTILES];
__device__ float g_psum[(size_t)Mc*NTILES];
__device__ float g_labv[Mc];
__device__ float g_nll[Mc];
__device__ float g_valid[Mc];
__device__ int   g_sep[Bc];
__device__ float g_bqkv[Lc*QKVN];          // fused QKV bias
// Transposed (N-major, K-contiguous) bf16 weights
__device__ bf16 g_WqkvT[(size_t)Lc*QKVN*Hc];
__device__ bf16 g_WoT[Lc*Hc*Hc];
__device__ bf16 g_WiT[(size_t)Lc*FFc*Hc];
__device__ bf16 g_WdT[(size_t)Lc*Hc*FFc];
__device__ bf16 g_WcT[(size_t)Vc*Hc];

// ---------------- small PTX helpers (compute_103-safe) ----------------
__device__ __forceinline__ uint32_t smem_to_u32(const void* smem_ptr) {
    uint32_t addr;
    asm("{ .reg .u64 tmp; cvta.to.shared.u64 tmp, %1; cvt.u32.u64 %0, tmp; }"
        : "=r"(addr) : "l"(smem_ptr));
    return addr;
}
__device__ __forceinline__ void cp16(uint32_t dst, const void* src, bool pred) {
    uint32_t sz = pred ? 16u : 0u;
    asm volatile("cp.async.cg.shared.global [%0], [%1], 16, %2;"
                 :: "r"(dst), "l"(src), "r"(sz));
}
#define CP_COMMIT() asm volatile("cp.async.commit_group;" ::: "memory")
#define CP_WAIT0()  asm volatile("cp.async.wait_group 0;" ::: "memory")
#define CP_WAIT1()  asm volatile("cp.async.wait_group 1;" ::: "memory")
#define CP_WAIT2()  asm volatile("cp.async.wait_group 2;" ::: "memory")

__device__ __forceinline__ void mma_bf16(float* c, const uint32_t* a,
                                         uint32_t b0, uint32_t b1) {
    asm volatile(
        "mma.sync.aligned.m16n8k16.row.col.f32.bf16.bf16.f32 "
        "{%0,%1,%2,%3}, {%4,%5,%6,%7}, {%8,%9}, {%0,%1,%2,%3};"
        : "+f"(c[0]), "+f"(c[1]), "+f"(c[2]), "+f"(c[3])
        : "r"(a[0]), "r"(a[1]), "r"(a[2]), "r"(a[3]), "r"(b0), "r"(b1));
}
__device__ __forceinline__ void ldmx4(uint32_t* r, uint32_t addr) {
    asm volatile("ldmatrix.sync.aligned.m8n8.x4.shared.b16 {%0,%1,%2,%3}, [%4];"
        : "=r"(r[0]), "=r"(r[1]), "=r"(r[2]), "=r"(r[3]) : "r"(addr));
}
__device__ __forceinline__ void ldmx2(uint32_t* r, uint32_t addr) {
    asm volatile("ldmatrix.sync.aligned.m8n8.x2.shared.b16 {%0,%1}, [%2];"
        : "=r"(r[0]), "=r"(r[1]) : "r"(addr));
}

__device__ __forceinline__ float gelu_exact(float v) {
    return 0.5f * v * (1.0f + erff(v * 0.70710678118654752f));
}

// ---------------- Batched weight transpose + bf16 conversion (bf162 stores) ----------------
__global__ void transpose_bf16_b(const float* __restrict__ in, bf16* __restrict__ out,
                                 int K, int N, size_t inStride, size_t outStride)
{
    __shared__ float tile[64][33];
    in  += (size_t)blockIdx.z * inStride;
    out += (size_t)blockIdx.z * outStride;
    int kb = blockIdx.y * 64, nb = blockIdx.x * 32;
    int tx = threadIdx.x, ty = threadIdx.y;
    for (int i = ty; i < 64; i += 8) {
        int kk = kb + i, nn = nb + tx;
        tile[i][tx] = (kk < K && nn < N) ? in[(size_t)kk * N + nn] : 0.0f;
    }
    __syncthreads();
    for (int i = ty; i < 32; i += 8) {
        int nn = nb + i;
        int kk = kb + 2 * tx;
        if (nn < N && kk < K) {
            bf162 o;
            o.x = __float2bfloat16_rn(tile[2*tx][i]);
            o.y = __float2bfloat16_rn(tile[2*tx + 1][i]);
            *reinterpret_cast<bf162*>(out + (size_t)nn * K + kk) = o;
        }
    }
}

// ---------------- fused QKV bias ----------------
__global__ void build_qkv_bias(const float* __restrict__ bq, const float* __restrict__ bk,
                               const float* __restrict__ bv)
{
    int i = blockIdx.x * 256 + threadIdx.x;
    if (i < Lc * QKVN) {
        int l = i / QKVN, c = i % QKVN;
        float v;
        if (c < Hc)            v = bq[l*Hc + c];
        else if (c < 2*Hc)     v = bk[l*Hc + c - Hc];
        else                   v = bv[l*Hc + c - 2*Hc];
        g_bqkv[i] = v;
    }
}

// ---------------- [SEP] position per batch row ----------------
__global__ void sep_kernel(const int* __restrict__ ids) {
    int b = threadIdx.x;
    if (b < Bc) {
        int s = Sc - 1;
        for (int i = 0; i < Sc; i++) {
            if (ids[b*Sc + i] == SEPc) { s = i; break; }
        }
        g_sep[b] = s;
    }
}

// ---------------- Embedding + LayerNorm (dual fp32 + bf16 output) ----------------
__global__ void embed_ln_kernel(const int* __restrict__ ids,
                                const float* __restrict__ we,
                                const float* __restrict__ pe,
                                const float* __restrict__ te,
                                const float* __restrict__ gg,
                                const float* __restrict__ bb)
{
    int row = blockIdx.x;
    int s   = row % Sc;
    int tid = threadIdx.x;
    __shared__ float buf[Hc];
    __shared__ float wsum[8], wsq[8];
    int id = ids[row];
    float lsum = 0.f, lsq = 0.f;
    for (int j = tid; j < Hc; j += 256) {
        float val = we[(size_t)id*Hc + j] + pe[s*Hc + j] + te[j];
        buf[j] = val;
        lsum += val; lsq += val * val;
    }
#pragma unroll
    for (int o = 16; o > 0; o >>= 1) {
        lsum += __shfl_xor_sync(0xffffffffu, lsum, o);
        lsq  += __shfl_xor_sync(0xffffffffu, lsq,  o);
    }
    if ((tid & 31) == 0) { wsum[tid >> 5] = lsum; wsq[tid >> 5] = lsq; }
    __syncthreads();
    float ts = 0.f, tq = 0.f;
#pragma unroll
    for (int i = 0; i < 8; i++) { ts += wsum[i]; tq += wsq[i]; }
    float mean = ts * (1.0f/Hc);
    float var  = fmaxf(tq * (1.0f/Hc) - mean * mean, 0.f);
    float inv  = rsqrtf(var + LN_EPS);
    for (int j = tid; j < Hc; j += 256) {
        float o = (buf[j]-mean)*inv*gg[j] + bb[j];
        g_x[(size_t)row*Hc + j]  = o;
        g_xb[(size_t)row*Hc + j] = __float2bfloat16_rn(o);
    }
}

// ---------------- Residual add + LayerNorm, dual output ----------------
__global__ void add_ln_kernel(float* __restrict__ x, bf16* __restrict__ xb,
                              const float* __restrict__ t,
                              const float* __restrict__ gg, const float* __restrict__ bb)
{
    int row = blockIdx.x;
    int tid = threadIdx.x;
    __shared__ float buf[Hc];
    __shared__ float wsum[8], wsq[8];
    float lsum = 0.f, lsq = 0.f;
    for (int j = tid; j < Hc; j += 256) {
        float val = x[(size_t)row*Hc + j] + t[(size_t)row*Hc + j];
        buf[j] = val;
        lsum += val; lsq += val * val;
    }
#pragma unroll
    for (int o = 16; o > 0; o >>= 1) {
        lsum += __shfl_xor_sync(0xffffffffu, lsum, o);
        lsq  += __shfl_xor_sync(0xffffffffu, lsq,  o);
    }
    if ((tid & 31) == 0) { wsum[tid >> 5] = lsum; wsq[tid >> 5] = lsq; }
    __syncthreads();
    float ts = 0.f, tq = 0.f;
#pragma unroll
    for (int i = 0; i < 8; i++) { ts += wsum[i]; tq += wsq[i]; }
    float mean = ts * (1.0f/Hc);
    float var  = fmaxf(tq * (1.0f/Hc) - mean * mean, 0.f);
    float inv  = rsqrtf(var + LN_EPS);
    for (int j = tid; j < Hc; j += 256) {
        float o = (buf[j]-mean)*inv*gg[j] + bb[j];
        x[(size_t)row*Hc + j]  = o;
        xb[(size_t)row*Hc + j] = __float2bfloat16_rn(o);
    }
}

// ======================= mma.sync bf16 GEMM (4-stage pipeline + ldmatrix) =======================
#define STG_HW 5120            // halfwords per stage (128*40)
#define STG_B  10240           // bytes per stage
#define GEMM_SMEM_BYTES 81920  // 8 buffers (A0-3, B0-3)

template<int ACT, int OUTBF>
__global__ __launch_bounds__(256)
void tc_gemm(const bf16* __restrict__ A, const bf16* __restrict__ Bt,
             const float* __restrict__ bias, void* __restrict__ Cv,
             int M, int N, int K)
{
    extern __shared__ __align__(16) char smraw[];
    const uint32_t sbase = smem_to_u32(smraw);

    const int t    = threadIdx.x;
    const int lane = t & 31;
    const int w    = t >> 5;
    const int wm   = w & 3;
    const int wn   = w >> 2;
    const int m0   = blockIdx.y * 128;
    const int n0   = blockIdx.x * 128;
    const int nk   = K >> 5;

    float acc[2][8][4];
#pragma unroll
    for (int mt = 0; mt < 2; mt++)
#pragma unroll
        for (int nt = 0; nt < 8; nt++)
#pragma unroll
            for (int i = 0; i < 4; i++) acc[mt][nt][i] = 0.f;

    auto load_stage = [&](int c) {
        const int s  = c & 3;
        const int k0 = c << 5;
        const uint32_t aB = sbase + (uint32_t)s * STG_B;
        const uint32_t bB = sbase + 4u * STG_B + (uint32_t)s * STG_B;
#pragma unroll
        for (int i = 0; i < 2; i++) {
            int idx = t + i * 256;
            int row = idx >> 2, q = idx & 3;
            cp16(aB + (uint32_t)(row * 80 + q * 16),
                 A + (size_t)(m0 + row) * K + k0 + q * 8, true);
            int nr = n0 + row;
            bool p = nr < N;
            int nrc = p ? nr : 0;
            cp16(bB + (uint32_t)(row * 80 + q * 16),
                 Bt + (size_t)nrc * K + k0 + q * 8, p);
        }
        CP_COMMIT();
    };

    // ldmatrix per-thread address offsets (bytes within a stage)
    const int lane8 = lane & 7;
    uint32_t aoffB[2], boffB[4];
#pragma unroll
    for (int mt = 0; mt < 2; mt++) {
        int arow = wm * 32 + mt * 16 + ((lane >> 3) & 1) * 8 + lane8;
        int acol = (lane >> 4) * 8;
        aoffB[mt] = (uint32_t)(arow * 40 + acol) * 2;
    }
#pragma unroll
    for (int jp = 0; jp < 4; jp++) {
        int brow = wn * 64 + jp * 16 + ((lane >> 4) & 1) * 8 + lane8;
        int bcol = ((lane >> 3) & 1) * 8;
        boffB[jp] = (uint32_t)(brow * 40 + bcol) * 2;
    }

    load_stage(0);
    if (nk > 1) load_stage(1);
    if (nk > 2) load_stage(2);
    for (int c = 0; c < nk; c++) {
        if (c + 2 < nk)      { CP_WAIT2(); }
        else if (c + 1 < nk) { CP_WAIT1(); }
        else                 { CP_WAIT0(); }
        __syncthreads();
        if (c + 3 < nk) load_stage(c + 3);

        const int s = c & 3;
        const uint32_t aStage = sbase + (uint32_t)s * STG_B;
        const uint32_t bStage = sbase + 4u * STG_B + (uint32_t)s * STG_B;
#pragma unroll
        for (int ks = 0; ks < 2; ks++) {
            uint32_t af[2][4];
            ldmx4(af[0], aStage + aoffB[0] + ks * 32);
            ldmx4(af[1], aStage + aoffB[1] + ks * 32);
#pragma unroll
            for (int jp = 0; jp < 4; jp++) {
                uint32_t bf[4];
                ldmx4(bf, bStage + boffB[jp] + ks * 32);
                mma_bf16(acc[0][2*jp],     af[0], bf[0], bf[1]);
                mma_bf16(acc[1][2*jp],     af[1], bf[0], bf[1]);
                mma_bf16(acc[0][2*jp + 1], af[0], bf[2], bf[3]);
                mma_bf16(acc[1][2*jp + 1], af[1], bf[2], bf[3]);
            }
        }
        // (no trailing barrier: next iteration's post-wait barrier orders buffer reuse)
    }

    const int lrow = lane >> 2;
    const int lk   = 2 * (lane & 3);
    float* Cf = (float*)Cv;
    bf16*  Cb = (bf16*)Cv;
#pragma unroll
    for (int mt = 0; mt < 2; mt++) {
        int rlo = m0 + wm * 32 + mt * 16 + lrow;
        int rhi = rlo + 8;
#pragma unroll
        for (int nt = 0; nt < 8; nt++) {
            int col = n0 + wn * 64 + nt * 8 + lk;
            if (col < N) {
                float b0v = bias[col], b1v = bias[col + 1];
                float v0 = acc[mt][nt][0] + b0v;
                float v1 = acc[mt][nt][1] + b1v;
                float v2 = acc[mt][nt][2] + b0v;
                float v3 = acc[mt][nt][3] + b1v;
                if (ACT == 1) {
                    v0 = gelu_exact(v0); v1 = gelu_exact(v1);
                    v2 = gelu_exact(v2); v3 = gelu_exact(v3);
                }
                if (OUTBF) {
                    bf162 lo; lo.x = __float2bfloat16_rn(v0); lo.y = __float2bfloat16_rn(v1);
                    bf162 hi; hi.x = __float2bfloat16_rn(v2); hi.y = __float2bfloat16_rn(v3);
                    *reinterpret_cast<bf162*>(Cb + (size_t)rlo * N + col) = lo;
                    *reinterpret_cast<bf162*>(Cb + (size_t)rhi * N + col) = hi;
                } else {
                    float2 lo; lo.x = v0; lo.y = v1;
                    float2 hi; hi.x = v2; hi.y = v3;
                    *reinterpret_cast<float2*>(Cf + (size_t)rlo * N + col) = lo;
                    *reinterpret_cast<float2*>(Cf + (size_t)rhi * N + col) = hi;
                }
            }
        }
    }
}

// ======================= Classifier GEMM + fused log-softmax partials (4-stage) =======================
__global__ __launch_bounds__(256)
void tc_gemm_loss(const bf16* __restrict__ A, const bf16* __restrict__ Bt,
                  const float* __restrict__ bias, const int* __restrict__ labels,
                  int M, int N, int K)
{
    extern __shared__ __align__(16) char smraw[];
    const uint32_t sbase = smem_to_u32(smraw);
    __shared__ float sMx[128][2];
    __shared__ float sSm[128][2];

    const int t    = threadIdx.x;
    const int lane = t & 31;
    const int w    = t >> 5;
    const int wm   = w & 3;
    const int wn   = w >> 2;
    const int mBase = blockIdx.y * 128;
    const int nBase = blockIdx.x * 128;
    const int nk   = K >> 5;

    float acc[2][8][4];
#pragma unroll
    for (int mt = 0; mt < 2; mt++)
#pragma unroll
        for (int nt = 0; nt < 8; nt++)
#pragma unroll
            for (int i = 0; i < 4; i++) acc[mt][nt][i] = 0.f;

    auto load_stage = [&](int c) {
        const int s  = c & 3;
        const int k0 = c << 5;
        const uint32_t aB = sbase + (uint32_t)s * STG_B;
        const uint32_t bB = sbase + 4u * STG_B + (uint32_t)s * STG_B;
#pragma unroll
        for (int i = 0; i < 2; i++) {
            int idx = t + i * 256;
            int row = idx >> 2, q = idx & 3;
            cp16(aB + (uint32_t)(row * 80 + q * 16),
                 A + (size_t)(mBase + row) * K + k0 + q * 8, true);
            int nr = nBase + row;
            bool p = nr < N;
            int nrc = p ? nr : 0;
            cp16(bB + (uint32_t)(row * 80 + q * 16),
                 Bt + (size_t)nrc * K + k0 + q * 8, p);
        }
        CP_COMMIT();
    };

    const int lane8 = lane & 7;
    uint32_t aoffB[2], boffB[4];
#pragma unroll
    for (int mt = 0; mt < 2; mt++) {
        int arow = wm * 32 + mt * 16 + ((lane >> 3) & 1) * 8 + lane8;
        int acol = (lane >> 4) * 8;
        aoffB[mt] = (uint32_t)(arow * 40 + acol) * 2;
    }
#pragma unroll
    for (int jp = 0; jp < 4; jp++) {
        int brow = wn * 64 + jp * 16 + ((lane >> 4) & 1) * 8 + lane8;
        int bcol = ((lane >> 3) & 1) * 8;
        boffB[jp] = (uint32_t)(brow * 40 + bcol) * 2;
    }

    const int lrow = lane >> 2;
    const int lk   = 2 * (lane & 3);

    load_stage(0);
    if (nk > 1) load_stage(1);
    if (nk > 2) load_stage(2);
    for (int c = 0; c < nk; c++) {
        if (c + 2 < nk)      { CP_WAIT2(); }
        else if (c + 1 < nk) { CP_WAIT1(); }
        else                 { CP_WAIT0(); }
        __syncthreads();
        if (c + 3 < nk) load_stage(c + 3);

        const int s = c & 3;
        const uint32_t aStage = sbase + (uint32_t)s * STG_B;
        const uint32_t bStage = sbase + 4u * STG_B + (uint32_t)s * STG_B;
#pragma unroll
        for (int ks = 0; ks < 2; ks++) {
            uint32_t af[2][4];
            ldmx4(af[0], aStage + aoffB[0] + ks * 32);
            ldmx4(af[1], aStage + aoffB[1] + ks * 32);
#pragma unroll
            for (int jp = 0; jp < 4; jp++) {
                uint32_t bf[4];
                ldmx4(bf, bStage + boffB[jp] + ks * 32);
                mma_bf16(acc[0][2*jp],     af[0], bf[0], bf[1]);
                mma_bf16(acc[1][2*jp],     af[1], bf[0], bf[1]);
                mma_bf16(acc[0][2*jp + 1], af[0], bf[2], bf[3]);
                mma_bf16(acc[1][2*jp + 1], af[1], bf[2], bf[3]);
            }
        }
    }
    __syncthreads();

    // ---- loss epilogue ----
    float vmax[2][2];
#pragma unroll
    for (int mt = 0; mt < 2; mt++) { vmax[mt][0] = -3.4e38f; vmax[mt][1] = -3.4e38f; }
#pragma unroll
    for (int mt = 0; mt < 2; mt++)
#pragma unroll
        for (int nt = 0; nt < 8; nt++) {
            int col = nBase + wn * 64 + nt * 8 + lk;
            float b0v = (col     < N) ? bias[col]     : 0.f;
            float b1v = (col + 1 < N) ? bias[col + 1] : 0.f;
            float v0 = (col     < N) ? acc[mt][nt][0] + b0v : -3.4e38f;
            float v1 = (col + 1 < N) ? acc[mt][nt][1] + b1v : -3.4e38f;
            float v2 = (col     < N) ? acc[mt][nt][2] + b0v : -3.4e38f;
            float v3 = (col + 1 < N) ? acc[mt][nt][3] + b1v : -3.4e38f;
            acc[mt][nt][0] = v0; acc[mt][nt][1] = v1;
            acc[mt][nt][2] = v2; acc[mt][nt][3] = v3;
            vmax[mt][0] = fmaxf(vmax[mt][0], fmaxf(v0, v1));
            vmax[mt][1] = fmaxf(vmax[mt][1], fmaxf(v2, v3));
        }
#pragma unroll
    for (int mt = 0; mt < 2; mt++)
#pragma unroll
        for (int hh = 0; hh < 2; hh++) {
            vmax[mt][hh] = fmaxf(vmax[mt][hh], __shfl_xor_sync(0xffffffffu, vmax[mt][hh], 1));
            vmax[mt][hh] = fmaxf(vmax[mt][hh], __shfl_xor_sync(0xffffffffu, vmax[mt][hh], 2));
        }
#pragma unroll
    for (int mt = 0; mt < 2; mt++) {
        int rin = wm * 32 + mt * 16 + lrow;
        sMx[rin][wn]     = vmax[mt][0];
        sMx[rin + 8][wn] = vmax[mt][1];
    }
    __syncthreads();
    float rmax[2][2], rsum[2][2];
#pragma unroll
    for (int mt = 0; mt < 2; mt++) {
        int rin = wm * 32 + mt * 16 + lrow;
        rmax[mt][0] = fmaxf(sMx[rin][0],     sMx[rin][1]);
        rmax[mt][1] = fmaxf(sMx[rin + 8][0], sMx[rin + 8][1]);
        rsum[mt][0] = 0.f; rsum[mt][1] = 0.f;
    }
#pragma unroll
    for (int mt = 0; mt < 2; mt++)
#pragma unroll
        for (int nt = 0; nt < 8; nt++) {
            rsum[mt][0] += __expf(acc[mt][nt][0] - rmax[mt][0])
                         + __expf(acc[mt][nt][1] - rmax[mt][0]);
            rsum[mt][1] += __expf(acc[mt][nt][2] - rmax[mt][1])
                         + __expf(acc[mt][nt][3] - rmax[mt][1]);
        }
#pragma unroll
    for (int mt = 0; mt < 2; mt++)
#pragma unroll
        for (int hh = 0; hh < 2; hh++) {
            rsum[mt][hh] += __shfl_xor_sync(0xffffffffu, rsum[mt][hh], 1);
            rsum[mt][hh] += __shfl_xor_sync(0xffffffffu, rsum[mt][hh], 2);
        }
#pragma unroll
    for (int mt = 0; mt < 2; mt++) {
        int rin = wm * 32 + mt * 16 + lrow;
        sSm[rin][wn]     = rsum[mt][0];
        sSm[rin + 8][wn] = rsum[mt][1];
    }
    __syncthreads();
    if (wn == 0 && (lane & 3) == 0) {
#pragma unroll
        for (int mt = 0; mt < 2; mt++) {
            int rin = wm * 32 + mt * 16 + lrow;
            int gr0 = mBase + rin, gr1 = gr0 + 8;
            g_pmax[(size_t)gr0 * NTILES + blockIdx.x] = rmax[mt][0];
            g_psum[(size_t)gr0 * NTILES + blockIdx.x] = sSm[rin][0] + sSm[rin][1];
            g_pmax[(size_t)gr1 * NTILES + blockIdx.x] = rmax[mt][1];
            g_psum[(size_t)gr1 * NTILES + blockIdx.x] = sSm[rin + 8][0] + sSm[rin + 8][1];
        }
    }
#pragma unroll
    for (int mt = 0; mt < 2; mt++) {
        int rin = wm * 32 + mt * 16 + lrow;
        int gr0 = mBase + rin, gr1 = gr0 + 8;
        int lab0 = labels[gr0], lab1 = labels[gr1];
#pragma unroll
        for (int nt = 0; nt < 8; nt++) {
            int col = nBase + wn * 64 + nt * 8 + lk;
            if (col == lab0)     g_labv[gr0] = acc[mt][nt][0];
            if (col + 1 == lab0) g_labv[gr0] = acc[mt][nt][1];
            if (col == lab1)     g_labv[gr1] = acc[mt][nt][2];
            if (col + 1 == lab1) g_labv[gr1] = acc[mt][nt][3];
        }
    }
}

// ---------------- merge loss partials: one warp per row ----------------
__global__ void loss_merge(const int* __restrict__ labels)
{
    int row  = (blockIdx.x * blockDim.x + threadIdx.x) >> 5;
    int lane = threadIdx.x & 31;
    if (row >= Mc) return;
    const float* pm = g_pmax + (size_t)row * NTILES;
    const float* ps = g_psum + (size_t)row * NTILES;
    float M = -3.4e38f;
    for (int i = lane; i < NTILES; i += 32) M = fmaxf(M, pm[i]);
#pragma unroll
    for (int o = 16; o > 0; o >>= 1) M = fmaxf(M, __shfl_xor_sync(0xffffffffu, M, o));
    float S = 0.f;
    for (int i = lane; i < NTILES; i += 32) S += ps[i] * __expf(pm[i] - M);
#pragma unroll
    for (int o = 16; o > 0; o >>= 1) S += __shfl_xor_sync(0xffffffffu, S, o);
    if (lane == 0) {
        int lab = labels[row];
        if (lab >= 0) {
            g_nll[row]   = (M + __logf(S)) - g_labv[row];
            g_valid[row] = 1.0f;
        } else {
            g_nll[row]   = 0.0f;
            g_valid[row] = 0.0f;
        }
    }
}

// ======================= Tensor-core attention (bf16 in-place score/P buffer, 2 CTAs/SM) =======================
#define AT_SQ    0
#define AT_SKV   2560
#define AT_SP    19968
#define AT_SINV  53248
#define AT_SMEM  53504

__global__ __launch_bounds__(256, 2)
void attn3_kernel(const bf16* __restrict__ qkv, bf16* __restrict__ ctx)
{
    extern __shared__ __align__(16) char sm[];
    uint16_t* sQ  = (uint16_t*)(sm + AT_SQ);
    uint16_t* sK  = (uint16_t*)(sm + AT_SKV);
    uint16_t* sVT = (uint16_t*)(sm + AT_SKV);
    bf16*     sSP = (bf16*)    (sm + AT_SP);
    float*    sInv= (float*)   (sm + AT_SINV);
    const uint32_t smb = smem_to_u32(sm);
    const uint32_t sQa = smb + AT_SQ;
    const uint32_t sKa = smb + AT_SKV;
    const uint32_t sVa = smb + AT_SKV;
    const uint32_t sPa = smb + AT_SP;

    const int t = threadIdx.x, lane = t & 31, w = t >> 5;
    const int q0 = blockIdx.x * 32;
    const int h  = blockIdx.y;
    const int b  = blockIdx.z;
    const int sp = g_sep[b];
    const int lrow = lane >> 2;
    const int lk   = 2 * (lane & 3);
    const int lane8 = lane & 7;
    const int Lmax = max(q0 + 31, sp);
    const int nch  = (Lmax >> 7) + 1;

    const bf16* qbase = qkv + (size_t)(b * Sc + q0) * QKVN + h * DHc;
    const bf16* kbase = qkv + (size_t)(b * Sc) * QKVN + Hc + h * DHc;
    const bf16* vbase = qkv + (size_t)(b * Sc) * QKVN + 2 * Hc + h * DHc;

    uint32_t aoffQ[2], aoffP[2];
#pragma unroll
    for (int mt = 0; mt < 2; mt++) {
        int arow = mt * 16 + ((lane >> 3) & 1) * 8 + lane8;
        int acol = (lane >> 4) * 8;
        aoffQ[mt] = (uint32_t)(arow * 40 + acol) * 2;
        aoffP[mt] = (uint32_t)(arow * 520 + acol) * 2;
    }
    const uint32_t boffK = (uint32_t)((w * 16 + ((lane >> 4) & 1) * 8 + lane8) * 40
                                      + ((lane >> 3) & 1) * 8) * 2;
    const uint32_t boffV = (uint32_t)((w * 8 + lane8) * 136 + ((lane >> 3) & 1) * 8) * 2;

#pragma unroll
    for (int i = 0; i < 2; i++) {
        int idx = t + i * 256;
        int r = idx >> 4, cg = idx & 15;
        uint2 v = *reinterpret_cast<const uint2*>(qbase + (size_t)r * QKVN + cg * 4);
        *reinterpret_cast<uint2*>(sQ + r * 40 + cg * 4) = v;
    }
    __syncthreads();

    for (int c = 0; c < nch; c++) {
        const int kb0 = c * 128;
#pragma unroll
        for (int i = 0; i < 8; i++) {
            int idx = t + i * 256;
            int r = idx >> 4, cg = idx & 15;
            uint2 v = *reinterpret_cast<const uint2*>(kbase + (size_t)(kb0 + r) * QKVN + cg * 4);
            *reinterpret_cast<uint2*>(sK + r * 40 + cg * 4) = v;
        }
        __syncthreads();

        float sacc[2][2][4];
#pragma unroll
        for (int mt = 0; mt < 2; mt++)
#pragma unroll
            for (int nt = 0; nt < 2; nt++)
#pragma unroll
                for (int i = 0; i < 4; i++) sacc[mt][nt][i] = 0.f;

#pragma unroll
        for (int ks = 0; ks < 4; ks++) {
            uint32_t af[2][4];
            ldmx4(af[0], sQa + aoffQ[0] + ks * 32);
            ldmx4(af[1], sQa + aoffQ[1] + ks * 32);
            uint32_t bf[4];
            ldmx4(bf, sKa + boffK + ks * 32);
            mma_bf16(sacc[0][0], af[0], bf[0], bf[1]);
            mma_bf16(sacc[1][0], af[1], bf[0], bf[1]);
            mma_bf16(sacc[0][1], af[0], bf[2], bf[3]);
            mma_bf16(sacc[1][1], af[1], bf[2], bf[3]);
        }
#pragma unroll
        for (int mt = 0; mt < 2; mt++) {
            const int r = mt * 16 + lrow;
#pragma unroll
            for (int nt = 0; nt < 2; nt++) {
                const int kcol = kb0 + w * 16 + nt * 8 + lk;
                bf162 lo, hi;
                lo.x = __float2bfloat16_rn(sacc[mt][nt][0] * 0.125f);
                lo.y = __float2bfloat16_rn(sacc[mt][nt][1] * 0.125f);
                hi.x = __float2bfloat16_rn(sacc[mt][nt][2] * 0.125f);
                hi.y = __float2bfloat16_rn(sacc[mt][nt][3] * 0.125f);
                *reinterpret_cast<bf162*>(sSP + r * 520 + kcol) = lo;
                *reinterpret_cast<bf162*>(sSP + (r + 8) * 520 + kcol) = hi;
            }
        }
        __syncthreads();
    }

    {
        const int r = t >> 3, sub = t & 7;
        const int Lk = max(q0 + r, sp);
        const int jmax = nch * 128;
        float m = -3.4e38f;
        for (int j = sub; j <= Lk; j += 8) m = fmaxf(m, __bfloat162float(sSP[r * 520 + j]));
#pragma unroll
        for (int msk = 1; msk < 8; msk <<= 1)
            m = fmaxf(m, __shfl_xor_sync(0xffffffffu, m, msk));
        float sum = 0.f;
        for (int j = sub; j < jmax; j += 8) {
            if (j <= Lk) {
                float e = __expf(__bfloat162float(sSP[r * 520 + j]) - m);
                sSP[r * 520 + j] = __float2bfloat16_rn(e);
                sum += e;
            } else {
                sSP[r * 520 + j] = __float2bfloat16_rn(0.f);
            }
        }
#pragma unroll
        for (int msk = 1; msk < 8; msk <<= 1)
            sum += __shfl_xor_sync(0xffffffffu, sum, msk);
        if (sub == 0) sInv[r] = 1.0f / sum;
    }
    __syncthreads();

    float cacc[2][4];
#pragma unroll
    for (int mt = 0; mt < 2; mt++)
#pragma unroll
        for (int i = 0; i < 4; i++) cacc[mt][i] = 0.f;

    for (int c = 0; c < nch; c++) {
        const int kb0 = c * 128;
#pragma unroll
        for (int i = 0; i < 8; i++) {
            int idx = t + i * 256;
            int kpos = idx >> 4, dg = idx & 15;
            uint2 v = *reinterpret_cast<const uint2*>(vbase + (size_t)(kb0 + kpos) * QKVN + dg * 4);
            sVT[(dg * 4 + 0) * 136 + kpos] = (uint16_t)(v.x);
            sVT[(dg * 4 + 1) * 136 + kpos] = (uint16_t)(v.x >> 16);
            sVT[(dg * 4 + 2) * 136 + kpos] = (uint16_t)(v.y);
            sVT[(dg * 4 + 3) * 136 + kpos] = (uint16_t)(v.y >> 16);
        }
        __syncthreads();
#pragma unroll
        for (int ks = 0; ks < 8; ks++) {
            uint32_t af[2][4];
            ldmx4(af[0], sPa + aoffP[0] + (kb0 + ks * 16) * 2);
            ldmx4(af[1], sPa + aoffP[1] + (kb0 + ks * 16) * 2);
            uint32_t bv[2];
            ldmx2(bv, sVa + boffV + ks * 32);
            mma_bf16(cacc[0], af[0], bv[0], bv[1]);
            mma_bf16(cacc[1], af[1], bv[0], bv[1]);
        }
        __syncthreads();
    }
#pragma unroll
    for (int mt = 0; mt < 2; mt++) {
        const int r = mt * 16 + lrow;
        const float inv0 = sInv[r], inv1 = sInv[r + 8];
        const int d0 = w * 8 + lk;
        bf162 lo, hi;
        lo.x = __float2bfloat16_rn(cacc[mt][0] * inv0);
        lo.y = __float2bfloat16_rn(cacc[mt][1] * inv0);
        hi.x = __float2bfloat16_rn(cacc[mt][2] * inv1);
        hi.y = __float2bfloat16_rn(cacc[mt][3] * inv1);
        *reinterpret_cast<bf162*>(ctx + (size_t)(b * Sc + q0 + r)     * Hc + h * DHc + d0) = lo;
        *reinterpret_cast<bf162*>(ctx + (size_t)(b * Sc + q0 + r + 8) * Hc + h * DHc + d0) = hi;
    }
}

// ---------------- Deterministic final reduction ----------------
__global__ void loss_reduce_kernel(float* __restrict__ out)
{
    __shared__ float rs[1024];
    __shared__ float rc[1024];
    int tid = threadIdx.x;
    float s = 0.f, c = 0.f;
    for (int i = tid; i < Mc; i += 1024) { s += g_nll[i]; c += g_valid[i]; }
    rs[tid] = s; rc[tid] = c; __syncthreads();
    for (int o = 512; o > 0; o >>= 1) {
        if (tid < o) { rs[tid] += rs[tid+o]; rc[tid] += rc[tid+o]; }
        __syncthreads();
    }
    if (tid == 0) out[0] = rs[0] / fmaxf(rc[0], 1.0f);
}

// ---------------- Host orchestration ----------------
static void run_tr_b(const float* in, bf16* out, int K, int N,
                     size_t inStride, size_t outStride, int layers)
{
    dim3 g((N + 31) / 32, (K + 63) / 64, layers);
    transpose_bf16_b<<<g, dim3(32, 8)>>>(in, out, K, N, inStride, outStride);
}

template<int ACT, int OUTBF>
static void run_gemm_t(const bf16* A, const bf16* Bt, const float* bias, void* C,
                       int M, int N, int K)
{
    dim3 grid((N + 127) / 128, M / 128);
    tc_gemm<ACT, OUTBF><<<grid, 256, GEMM_SMEM_BYTES>>>(A, Bt, bias, C, M, N, K);
}

extern "C" void kernel_launch(void* const* d_in, const int* in_sizes, int n_in,
                              void* d_out, int out_size)
{
    (void)in_sizes; (void)n_in; (void)out_size;

    const int*   ids      = (const int*)  d_in[0];
    const int*   labels   = (const int*)  d_in[1];
    const float* word_emb = (const float*)d_in[2];
    const float* pos_emb  = (const float*)d_in[3];
    const float* type_emb = (const float*)d_in[4];
    const float* eg       = (const float*)d_in[5];
    const float* eb       = (const float*)d_in[6];
    const float* Wq       = (const float*)d_in[7];
    const float* bq       = (const float*)d_in[8];
    const float* Wk       = (const float*)d_in[9];
    const float* bk       = (const float*)d_in[10];
    const float* Wv       = (const float*)d_in[11];
    const float* bv       = (const float*)d_in[12];
    const float* Wo       = (const float*)d_in[13];
    const float* bo       = (const float*)d_in[14];
    const float* l1g      = (const float*)d_in[15];
    const float* l1b      = (const float*)d_in[16];
    const float* Wi       = (const float*)d_in[17];
    const float* bi       = (const float*)d_in[18];
    const float* Wd       = (const float*)d_in[19];
    const float* bd       = (const float*)d_in[20];
    const float* l2g      = (const float*)d_in[21];
    const float* l2b      = (const float*)d_in[22];
    const float* Wc       = (const float*)d_in[23];
    const float* bc       = (const float*)d_in[24];

    // SMEM opt-ins for every kernel above the 48KB default
    cudaFuncSetAttribute(attn3_kernel,  cudaFuncAttributeMaxDynamicSharedMemorySize, AT_SMEM);
    cudaFuncSetAttribute(tc_gemm<0,0>,  cudaFuncAttributeMaxDynamicSharedMemorySize, GEMM_SMEM_BYTES);
    cudaFuncSetAttribute(tc_gemm<0,1>,  cudaFuncAttributeMaxDynamicSharedMemorySize, GEMM_SMEM_BYTES);
    cudaFuncSetAttribute(tc_gemm<1,1>,  cudaFuncAttributeMaxDynamicSharedMemorySize, GEMM_SMEM_BYTES);
    cudaFuncSetAttribute(tc_gemm_loss,  cudaFuncAttributeMaxDynamicSharedMemorySize, GEMM_SMEM_BYTES);

    void* p;
    cudaGetSymbolAddress(&p, g_x);      float* px    = (float*)p;
    cudaGetSymbolAddress(&p, g_xb);     bf16*  pxb   = (bf16*)p;
    cudaGetSymbolAddress(&p, g_qkvb);   bf16*  pqkvb = (bf16*)p;
    cudaGetSymbolAddress(&p, g_ctxb);   bf16*  pctxb = (bf16*)p;
    cudaGetSymbolAddress(&p, g_proj);   float* pproj = (float*)p;
    cudaGetSymbolAddress(&p, g_ffnb);   bf16*  pffnb = (bf16*)p;
    cudaGetSymbolAddress(&p, g_bqkv);   float* pbqkv = (float*)p;
    cudaGetSymbolAddress(&p, g_WqkvT);  bf16*  pWqkvT= (bf16*)p;
    cudaGetSymbolAddress(&p, g_WoT);    bf16*  pWoT  = (bf16*)p;
    cudaGetSymbolAddress(&p, g_WiT);    bf16*  pWiT  = (bf16*)p;
    cudaGetSymbolAddress(&p, g_WdT);    bf16*  pWdT  = (bf16*)p;
    cudaGetSymbolAddress(&p, g_WcT);    bf16*  pWcT  = (bf16*)p;

    // Batched weight transposes (7 launches)
    const size_t HH = (size_t)Hc * Hc;
    run_tr_b(Wq, pWqkvT,                    Hc, Hc, HH, (size_t)QKVN*Hc, Lc);
    run_tr_b(Wk, pWqkvT + HH,               Hc, Hc, HH, (size_t)QKVN*Hc, Lc);
    run_tr_b(Wv, pWqkvT + 2*HH,             Hc, Hc, HH, (size_t)QKVN*Hc, Lc);
    run_tr_b(Wo, pWoT,                      Hc, Hc, HH, HH, Lc);
    run_tr_b(Wi, pWiT,  Hc, FFc, (size_t)Hc*FFc, (size_t)FFc*Hc, Lc);
    run_tr_b(Wd, pWdT,  FFc, Hc, (size_t)FFc*Hc, (size_t)Hc*FFc, Lc);
    run_tr_b(Wc, pWcT,  Hc, Vc,  0, 0, 1);

    build_qkv_bias<<<(Lc*QKVN + 255)/256, 256>>>(bq, bk, bv);
    sep_kernel<<<1, 32>>>(ids);
    embed_ln_kernel<<<Mc, 256>>>(ids, word_emb, pos_emb, type_emb, eg, eb);

    for (int l = 0; l < Lc; l++) {
        run_gemm_t<0,1>(pxb, pWqkvT + (size_t)l*QKVN*Hc, pbqkv + (size_t)l*QKVN,
                        pqkvb, Mc, QKVN, Hc);
        attn3_kernel<<<dim3(Sc/32, NHc, Bc), 256, AT_SMEM>>>(pqkvb, pctxb);
        run_gemm_t<0,0>(pctxb, pWoT + (size_t)l*HH, bo + (size_t)l*Hc, pproj, Mc, Hc, Hc);
        add_ln_kernel<<<Mc, 256>>>(px, pxb, pproj, l1g + (size_t)l*Hc, l1b + (size_t)l*Hc);
        run_gemm_t<1,1>(pxb, pWiT + (size_t)l*FFc*Hc, bi + (size_t)l*FFc, pffnb, Mc, FFc, Hc);
        run_gemm_t<0,0>(pffnb, pWdT + (size_t)l*Hc*FFc, bd + (size_t)l*Hc, pproj, Mc, Hc, FFc);
        add_ln_kernel<<<Mc, 256>>>(px, pxb, pproj, l2g + (size_t)l*Hc, l2b + (size_t)l*Hc);
    }

    // classifier + fused loss
    {
        dim3 grid(NTILES, Mc / 128);
        tc_gemm_loss<<<grid, 256, GEMM_SMEM_BYTES>>>(pxb, pWcT, bc, labels, Mc, Vc, Hc);
    }
    loss_merge<<<(Mc * 32 + 255) / 256, 256>>>(labels);
    loss_reduce_kernel<<<1, 1024>>>((float*)d_out);
}

// round 15
// speedup vs baseline: 1.0369x; 1.0369x over previous
#include <cuda_runtime.h>
#include <cuda_bf16.h>
#include <math.h>
#include <stdint.h>

// Problem constants
#define Lc 12
#define Hc 768
#define NHc 12
#define DHc 64
#define FFc 3072
#define Vc 21128
#define Sc 512
#define Bc 8
#define Mc (Bc*Sc)          // 4096 tokens
#define SEPc 102
#define LN_EPS 1e-12f
#define QKVN 2304
#define NTILES 166          // ceil(Vc/128)

typedef __nv_bfloat16 bf16;
typedef __nv_bfloat162 bf162;

// ---------------- Device scratch (static; no runtime allocation) ----------------
__device__ float g_x[Mc*Hc];               // fp32 residual stream
__device__ bf16  g_xb[Mc*Hc];              // bf16 copy of x (GEMM A operand)
__device__ bf16  g_qkvb[(size_t)Mc*QKVN];  // fused QKV output (bf16)
__device__ bf16  g_ctxb[Mc*Hc];            // attention output (bf16, feeds Wo)
__device__ float g_proj[Mc*Hc];            // fp32 GEMM output before residual+LN
__device__ bf16  g_ffnb[(size_t)Mc*FFc];   // GELU output (bf16, feeds Wd)
__device__ float g_pmax[(size_t)Mc*NTILES];
__device__ float g_psum[(size_t)Mc*NTILES];
__device__ float g_labv[Mc];
__device__ float g_nll[Mc];
__device__ float g_valid[Mc];
__device__ int   g_sep[Bc];
__device__ float g_bqkv[Lc*QKVN];          // fused QKV bias
// Transposed (N-major, K-contiguous) bf16 weights
__device__ bf16 g_WqkvT[(size_t)Lc*QKVN*Hc];
__device__ bf16 g_WoT[Lc*Hc*Hc];
__device__ bf16 g_WiT[(size_t)Lc*FFc*Hc];
__device__ bf16 g_WdT[(size_t)Lc*Hc*FFc];
__device__ bf16 g_WcT[(size_t)Vc*Hc];

// ---------------- small PTX helpers (compute_103-safe) ----------------
__device__ __forceinline__ uint32_t smem_to_u32(const void* smem_ptr) {
    uint32_t addr;
    asm("{ .reg .u64 tmp; cvta.to.shared.u64 tmp, %1; cvt.u32.u64 %0, tmp; }"
        : "=r"(addr) : "l"(smem_ptr));
    return addr;
}
__device__ __forceinline__ void cp16(uint32_t dst, const void* src, bool pred) {
    uint32_t sz = pred ? 16u : 0u;
    asm volatile("cp.async.cg.shared.global [%0], [%1], 16, %2;"
                 :: "r"(dst), "l"(src), "r"(sz));
}
#define CP_COMMIT() asm volatile("cp.async.commit_group;" ::: "memory")
#define CP_WAIT0()  asm volatile("cp.async.wait_group 0;" ::: "memory")
#define CP_WAIT1()  asm volatile("cp.async.wait_group 1;" ::: "memory")

__device__ __forceinline__ void mma_bf16(float* c, const uint32_t* a,
                                         uint32_t b0, uint32_t b1) {
    asm volatile(
        "mma.sync.aligned.m16n8k16.row.col.f32.bf16.bf16.f32 "
        "{%0,%1,%2,%3}, {%4,%5,%6,%7}, {%8,%9}, {%0,%1,%2,%3};"
        : "+f"(c[0]), "+f"(c[1]), "+f"(c[2]), "+f"(c[3])
        : "r"(a[0]), "r"(a[1]), "r"(a[2]), "r"(a[3]), "r"(b0), "r"(b1));
}
__device__ __forceinline__ void ldmx4(uint32_t* r, uint32_t addr) {
    asm volatile("ldmatrix.sync.aligned.m8n8.x4.shared.b16 {%0,%1,%2,%3}, [%4];"
        : "=r"(r[0]), "=r"(r[1]), "=r"(r[2]), "=r"(r[3]) : "r"(addr));
}
__device__ __forceinline__ void ldmx2(uint32_t* r, uint32_t addr) {
    asm volatile("ldmatrix.sync.aligned.m8n8.x2.shared.b16 {%0,%1}, [%2];"
        : "=r"(r[0]), "=r"(r[1]) : "r"(addr));
}

__device__ __forceinline__ float gelu_exact(float v) {
    return 0.5f * v * (1.0f + erff(v * 0.70710678118654752f));
}

// ---------------- Batched weight transpose + bf16 conversion (bf162 stores) ----------------
__global__ void transpose_bf16_b(const float* __restrict__ in, bf16* __restrict__ out,
                                 int K, int N, size_t inStride, size_t outStride)
{
    __shared__ float tile[64][33];
    in  += (size_t)blockIdx.z * inStride;
    out += (size_t)blockIdx.z * outStride;
    int kb = blockIdx.y * 64, nb = blockIdx.x * 32;
    int tx = threadIdx.x, ty = threadIdx.y;
    for (int i = ty; i < 64; i += 8) {
        int kk = kb + i, nn = nb + tx;
        tile[i][tx] = (kk < K && nn < N) ? in[(size_t)kk * N + nn] : 0.0f;
    }
    __syncthreads();
    for (int i = ty; i < 32; i += 8) {
        int nn = nb + i;
        int kk = kb + 2 * tx;
        if (nn < N && kk < K) {
            bf162 o;
            o.x = __float2bfloat16_rn(tile[2*tx][i]);
            o.y = __float2bfloat16_rn(tile[2*tx + 1][i]);
            *reinterpret_cast<bf162*>(out + (size_t)nn * K + kk) = o;
        }
    }
}

// ---------------- fused QKV bias ----------------
__global__ void build_qkv_bias(const float* __restrict__ bq, const float* __restrict__ bk,
                               const float* __restrict__ bv)
{
    int i = blockIdx.x * 256 + threadIdx.x;
    if (i < Lc * QKVN) {
        int l = i / QKVN, c = i % QKVN;
        float v;
        if (c < Hc)            v = bq[l*Hc + c];
        else if (c < 2*Hc)     v = bk[l*Hc + c - Hc];
        else                   v = bv[l*Hc + c - 2*Hc];
        g_bqkv[i] = v;
    }
}

// ---------------- [SEP] position per batch row ----------------
__global__ void sep_kernel(const int* __restrict__ ids) {
    int b = threadIdx.x;
    if (b < Bc) {
        int s = Sc - 1;
        for (int i = 0; i < Sc; i++) {
            if (ids[b*Sc + i] == SEPc) { s = i; break; }
        }
        g_sep[b] = s;
    }
}

// ---------------- Embedding + LayerNorm (dual fp32 + bf16 output) ----------------
__global__ void embed_ln_kernel(const int* __restrict__ ids,
                                const float* __restrict__ we,
                                const float* __restrict__ pe,
                                const float* __restrict__ te,
                                const float* __restrict__ gg,
                                const float* __restrict__ bb)
{
    int row = blockIdx.x;
    int s   = row % Sc;
    int tid = threadIdx.x;
    __shared__ float buf[Hc];
    __shared__ float wsum[8], wsq[8];
    int id = ids[row];
    float lsum = 0.f, lsq = 0.f;
    for (int j = tid; j < Hc; j += 256) {
        float val = we[(size_t)id*Hc + j] + pe[s*Hc + j] + te[j];
        buf[j] = val;
        lsum += val; lsq += val * val;
    }
#pragma unroll
    for (int o = 16; o > 0; o >>= 1) {
        lsum += __shfl_xor_sync(0xffffffffu, lsum, o);
        lsq  += __shfl_xor_sync(0xffffffffu, lsq,  o);
    }
    if ((tid & 31) == 0) { wsum[tid >> 5] = lsum; wsq[tid >> 5] = lsq; }
    __syncthreads();
    float ts = 0.f, tq = 0.f;
#pragma unroll
    for (int i = 0; i < 8; i++) { ts += wsum[i]; tq += wsq[i]; }
    float mean = ts * (1.0f/Hc);
    float var  = fmaxf(tq * (1.0f/Hc) - mean * mean, 0.f);
    float inv  = rsqrtf(var + LN_EPS);
    for (int j = tid; j < Hc; j += 256) {
        float o = (buf[j]-mean)*inv*gg[j] + bb[j];
        g_x[(size_t)row*Hc + j]  = o;
        g_xb[(size_t)row*Hc + j] = __float2bfloat16_rn(o);
    }
}

// ---------------- Residual add + LayerNorm, dual output ----------------
__global__ void add_ln_kernel(float* __restrict__ x, bf16* __restrict__ xb,
                              const float* __restrict__ t,
                              const float* __restrict__ gg, const float* __restrict__ bb)
{
    int row = blockIdx.x;
    int tid = threadIdx.x;
    __shared__ float buf[Hc];
    __shared__ float wsum[8], wsq[8];
    float lsum = 0.f, lsq = 0.f;
    for (int j = tid; j < Hc; j += 256) {
        float val = x[(size_t)row*Hc + j] + t[(size_t)row*Hc + j];
        buf[j] = val;
        lsum += val; lsq += val * val;
    }
#pragma unroll
    for (int o = 16; o > 0; o >>= 1) {
        lsum += __shfl_xor_sync(0xffffffffu, lsum, o);
        lsq  += __shfl_xor_sync(0xffffffffu, lsq,  o);
    }
    if ((tid & 31) == 0) { wsum[tid >> 5] = lsum; wsq[tid >> 5] = lsq; }
    __syncthreads();
    float ts = 0.f, tq = 0.f;
#pragma unroll
    for (int i = 0; i < 8; i++) { ts += wsum[i]; tq += wsq[i]; }
    float mean = ts * (1.0f/Hc);
    float var  = fmaxf(tq * (1.0f/Hc) - mean * mean, 0.f);
    float inv  = rsqrtf(var + LN_EPS);
    for (int j = tid; j < Hc; j += 256) {
        float o = (buf[j]-mean)*inv*gg[j] + bb[j];
        x[(size_t)row*Hc + j]  = o;
        xb[(size_t)row*Hc + j] = __float2bfloat16_rn(o);
    }
}

// ======================= mma.sync bf16 GEMM (3-stage pipeline + ldmatrix, 2 CTAs/SM) =======================
#define STG_HW 5120            // halfwords per stage (128*40)
#define STG_B  10240           // bytes per stage
#define GEMM_SMEM_BYTES 61440  // 6 buffers (A0-2, B0-2)

template<int ACT, int OUTBF>
__global__ __launch_bounds__(256, 2)
void tc_gemm(const bf16* __restrict__ A, const bf16* __restrict__ Bt,
             const float* __restrict__ bias, void* __restrict__ Cv,
             int M, int N, int K)
{
    extern __shared__ __align__(16) char smraw[];
    const uint32_t sbase = smem_to_u32(smraw);

    const int t    = threadIdx.x;
    const int lane = t & 31;
    const int w    = t >> 5;
    const int wm   = w & 3;
    const int wn   = w >> 2;
    const int m0   = blockIdx.y * 128;
    const int n0   = blockIdx.x * 128;
    const int nk   = K >> 5;

    float acc[2][8][4];
#pragma unroll
    for (int mt = 0; mt < 2; mt++)
#pragma unroll
        for (int nt = 0; nt < 8; nt++)
#pragma unroll
            for (int i = 0; i < 4; i++) acc[mt][nt][i] = 0.f;

    auto load_stage = [&](int c) {
        const int s  = c % 3;
        const int k0 = c << 5;
        const uint32_t aB = sbase + (uint32_t)s * STG_B;
        const uint32_t bB = sbase + 3u * STG_B + (uint32_t)s * STG_B;
#pragma unroll
        for (int i = 0; i < 2; i++) {
            int idx = t + i * 256;
            int row = idx >> 2, q = idx & 3;
            cp16(aB + (uint32_t)(row * 80 + q * 16),
                 A + (size_t)(m0 + row) * K + k0 + q * 8, true);
            int nr = n0 + row;
            bool p = nr < N;
            int nrc = p ? nr : 0;
            cp16(bB + (uint32_t)(row * 80 + q * 16),
                 Bt + (size_t)nrc * K + k0 + q * 8, p);
        }
        CP_COMMIT();
    };

    // ldmatrix per-thread address offsets (bytes within a stage)
    const int lane8 = lane & 7;
    uint32_t aoffB[2], boffB[4];
#pragma unroll
    for (int mt = 0; mt < 2; mt++) {
        int arow = wm * 32 + mt * 16 + ((lane >> 3) & 1) * 8 + lane8;
        int acol = (lane >> 4) * 8;
        aoffB[mt] = (uint32_t)(arow * 40 + acol) * 2;
    }
#pragma unroll
    for (int jp = 0; jp < 4; jp++) {
        int brow = wn * 64 + jp * 16 + ((lane >> 4) & 1) * 8 + lane8;
        int bcol = ((lane >> 3) & 1) * 8;
        boffB[jp] = (uint32_t)(brow * 40 + bcol) * 2;
    }

    load_stage(0);
    if (nk > 1) load_stage(1);
    for (int c = 0; c < nk; c++) {
        if (c + 1 < nk) { CP_WAIT1(); } else { CP_WAIT0(); }
        __syncthreads();
        if (c + 2 < nk) load_stage(c + 2);

        const int s = c % 3;
        const uint32_t aStage = sbase + (uint32_t)s * STG_B;
        const uint32_t bStage = sbase + 3u * STG_B + (uint32_t)s * STG_B;
#pragma unroll
        for (int ks = 0; ks < 2; ks++) {
            uint32_t af[2][4];
            ldmx4(af[0], aStage + aoffB[0] + ks * 32);
            ldmx4(af[1], aStage + aoffB[1] + ks * 32);
#pragma unroll
            for (int jp = 0; jp < 4; jp++) {
                uint32_t bf[4];
                ldmx4(bf, bStage + boffB[jp] + ks * 32);
                mma_bf16(acc[0][2*jp],     af[0], bf[0], bf[1]);
                mma_bf16(acc[1][2*jp],     af[1], bf[0], bf[1]);
                mma_bf16(acc[0][2*jp + 1], af[0], bf[2], bf[3]);
                mma_bf16(acc[1][2*jp + 1], af[1], bf[2], bf[3]);
            }
        }
        // (no trailing barrier: next iteration's post-wait barrier orders buffer reuse)
    }

    const int lrow = lane >> 2;
    const int lk   = 2 * (lane & 3);
    float* Cf = (float*)Cv;
    bf16*  Cb = (bf16*)Cv;
#pragma unroll
    for (int mt = 0; mt < 2; mt++) {
        int rlo = m0 + wm * 32 + mt * 16 + lrow;
        int rhi = rlo + 8;
#pragma unroll
        for (int nt = 0; nt < 8; nt++) {
            int col = n0 + wn * 64 + nt * 8 + lk;
            if (col < N) {
                float b0v = bias[col], b1v = bias[col + 1];
                float v0 = acc[mt][nt][0] + b0v;
                float v1 = acc[mt][nt][1] + b1v;
                float v2 = acc[mt][nt][2] + b0v;
                float v3 = acc[mt][nt][3] + b1v;
                if (ACT == 1) {
                    v0 = gelu_exact(v0); v1 = gelu_exact(v1);
                    v2 = gelu_exact(v2); v3 = gelu_exact(v3);
                }
                if (OUTBF) {
                    bf162 lo; lo.x = __float2bfloat16_rn(v0); lo.y = __float2bfloat16_rn(v1);
                    bf162 hi; hi.x = __float2bfloat16_rn(v2); hi.y = __float2bfloat16_rn(v3);
                    *reinterpret_cast<bf162*>(Cb + (size_t)rlo * N + col) = lo;
                    *reinterpret_cast<bf162*>(Cb + (size_t)rhi * N + col) = hi;
                } else {
                    float2 lo; lo.x = v0; lo.y = v1;
                    float2 hi; hi.x = v2; hi.y = v3;
                    *reinterpret_cast<float2*>(Cf + (size_t)rlo * N + col) = lo;
                    *reinterpret_cast<float2*>(Cf + (size_t)rhi * N + col) = hi;
                }
            }
        }
    }
}

// ======================= Classifier GEMM + fused log-softmax partials =======================
__global__ __launch_bounds__(256, 2)
void tc_gemm_loss(const bf16* __restrict__ A, const bf16* __restrict__ Bt,
                  const float* __restrict__ bias, const int* __restrict__ labels,
                  int M, int N, int K)
{
    extern __shared__ __align__(16) char smraw[];
    const uint32_t sbase = smem_to_u32(smraw);
    __shared__ float sMx[128][2];
    __shared__ float sSm[128][2];

    const int t    = threadIdx.x;
    const int lane = t & 31;
    const int w    = t >> 5;
    const int wm   = w & 3;
    const int wn   = w >> 2;
    const int mBase = blockIdx.y * 128;
    const int nBase = blockIdx.x * 128;
    const int nk   = K >> 5;

    float acc[2][8][4];
#pragma unroll
    for (int mt = 0; mt < 2; mt++)
#pragma unroll
        for (int nt = 0; nt < 8; nt++)
#pragma unroll
            for (int i = 0; i < 4; i++) acc[mt][nt][i] = 0.f;

    auto load_stage = [&](int c) {
        const int s  = c % 3;
        const int k0 = c << 5;
        const uint32_t aB = sbase + (uint32_t)s * STG_B;
        const uint32_t bB = sbase + 3u * STG_B + (uint32_t)s * STG_B;
#pragma unroll
        for (int i = 0; i < 2; i++) {
            int idx = t + i * 256;
            int row = idx >> 2, q = idx & 3;
            cp16(aB + (uint32_t)(row * 80 + q * 16),
                 A + (size_t)(mBase + row) * K + k0 + q * 8, true);
            int nr = nBase + row;
            bool p = nr < N;
            int nrc = p ? nr : 0;
            cp16(bB + (uint32_t)(row * 80 + q * 16),
                 Bt + (size_t)nrc * K + k0 + q * 8, p);
        }
        CP_COMMIT();
    };

    const int lane8 = lane & 7;
    uint32_t aoffB[2], boffB[4];
#pragma unroll
    for (int mt = 0; mt < 2; mt++) {
        int arow = wm * 32 + mt * 16 + ((lane >> 3) & 1) * 8 + lane8;
        int acol = (lane >> 4) * 8;
        aoffB[mt] = (uint32_t)(arow * 40 + acol) * 2;
    }
#pragma unroll
    for (int jp = 0; jp < 4; jp++) {
        int brow = wn * 64 + jp * 16 + ((lane >> 4) & 1) * 8 + lane8;
        int bcol = ((lane >> 3) & 1) * 8;
        boffB[jp] = (uint32_t)(brow * 40 + bcol) * 2;
    }

    const int lrow = lane >> 2;
    const int lk   = 2 * (lane & 3);

    load_stage(0);
    if (nk > 1) load_stage(1);
    for (int c = 0; c < nk; c++) {
        if (c + 1 < nk) { CP_WAIT1(); } else { CP_WAIT0(); }
        __syncthreads();
        if (c + 2 < nk) load_stage(c + 2);

        const int s = c % 3;
        const uint32_t aStage = sbase + (uint32_t)s * STG_B;
        const uint32_t bStage = sbase + 3u * STG_B + (uint32_t)s * STG_B;
#pragma unroll
        for (int ks = 0; ks < 2; ks++) {
            uint32_t af[2][4];
            ldmx4(af[0], aStage + aoffB[0] + ks * 32);
            ldmx4(af[1], aStage + aoffB[1] + ks * 32);
#pragma unroll
            for (int jp = 0; jp < 4; jp++) {
                uint32_t bf[4];
                ldmx4(bf, bStage + boffB[jp] + ks * 32);
                mma_bf16(acc[0][2*jp],     af[0], bf[0], bf[1]);
                mma_bf16(acc[1][2*jp],     af[1], bf[0], bf[1]);
                mma_bf16(acc[0][2*jp + 1], af[0], bf[2], bf[3]);
                mma_bf16(acc[1][2*jp + 1], af[1], bf[2], bf[3]);
            }
        }
    }
    __syncthreads();

    // ---- loss epilogue ----
    float vmax[2][2];
#pragma unroll
    for (int mt = 0; mt < 2; mt++) { vmax[mt][0] = -3.4e38f; vmax[mt][1] = -3.4e38f; }
#pragma unroll
    for (int mt = 0; mt < 2; mt++)
#pragma unroll
        for (int nt = 0; nt < 8; nt++) {
            int col = nBase + wn * 64 + nt * 8 + lk;
            float b0v = (col     < N) ? bias[col]     : 0.f;
            float b1v = (col + 1 < N) ? bias[col + 1] : 0.f;
            float v0 = (col     < N) ? acc[mt][nt][0] + b0v : -3.4e38f;
            float v1 = (col + 1 < N) ? acc[mt][nt][1] + b1v : -3.4e38f;
            float v2 = (col     < N) ? acc[mt][nt][2] + b0v : -3.4e38f;
            float v3 = (col + 1 < N) ? acc[mt][nt][3] + b1v : -3.4e38f;
            acc[mt][nt][0] = v0; acc[mt][nt][1] = v1;
            acc[mt][nt][2] = v2; acc[mt][nt][3] = v3;
            vmax[mt][0] = fmaxf(vmax[mt][0], fmaxf(v0, v1));
            vmax[mt][1] = fmaxf(vmax[mt][1], fmaxf(v2, v3));
        }
#pragma unroll
    for (int mt = 0; mt < 2; mt++)
#pragma unroll
        for (int hh = 0; hh < 2; hh++) {
            vmax[mt][hh] = fmaxf(vmax[mt][hh], __shfl_xor_sync(0xffffffffu, vmax[mt][hh], 1));
            vmax[mt][hh] = fmaxf(vmax[mt][hh], __shfl_xor_sync(0xffffffffu, vmax[mt][hh], 2));
        }
#pragma unroll
    for (int mt = 0; mt < 2; mt++) {
        int rin = wm * 32 + mt * 16 + lrow;
        sMx[rin][wn]     = vmax[mt][0];
        sMx[rin + 8][wn] = vmax[mt][1];
    }
    __syncthreads();
    float rmax[2][2], rsum[2][2];
#pragma unroll
    for (int mt = 0; mt < 2; mt++) {
        int rin = wm * 32 + mt * 16 + lrow;
        rmax[mt][0] = fmaxf(sMx[rin][0],     sMx[rin][1]);
        rmax[mt][1] = fmaxf(sMx[rin + 8][0], sMx[rin + 8][1]);
        rsum[mt][0] = 0.f; rsum[mt][1] = 0.f;
    }
#pragma unroll
    for (int mt = 0; mt < 2; mt++)
#pragma unroll
        for (int nt = 0; nt < 8; nt++) {
            rsum[mt][0] += __expf(acc[mt][nt][0] - rmax[mt][0])
                         + __expf(acc[mt][nt][1] - rmax[mt][0]);
            rsum[mt][1] += __expf(acc[mt][nt][2] - rmax[mt][1])
                         + __expf(acc[mt][nt][3] - rmax[mt][1]);
        }
#pragma unroll
    for (int mt = 0; mt < 2; mt++)
#pragma unroll
        for (int hh = 0; hh < 2; hh++) {
            rsum[mt][hh] += __shfl_xor_sync(0xffffffffu, rsum[mt][hh], 1);
            rsum[mt][hh] += __shfl_xor_sync(0xffffffffu, rsum[mt][hh], 2);
        }
#pragma unroll
    for (int mt = 0; mt < 2; mt++) {
        int rin = wm * 32 + mt * 16 + lrow;
        sSm[rin][wn]     = rsum[mt][0];
        sSm[rin + 8][wn] = rsum[mt][1];
    }
    __syncthreads();
    if (wn == 0 && (lane & 3) == 0) {
#pragma unroll
        for (int mt = 0; mt < 2; mt++) {
            int rin = wm * 32 + mt * 16 + lrow;
            int gr0 = mBase + rin, gr1 = gr0 + 8;
            g_pmax[(size_t)gr0 * NTILES + blockIdx.x] = rmax[mt][0];
            g_psum[(size_t)gr0 * NTILES + blockIdx.x] = sSm[rin][0] + sSm[rin][1];
            g_pmax[(size_t)gr1 * NTILES + blockIdx.x] = rmax[mt][1];
            g_psum[(size_t)gr1 * NTILES + blockIdx.x] = sSm[rin + 8][0] + sSm[rin + 8][1];
        }
    }
#pragma unroll
    for (int mt = 0; mt < 2; mt++) {
        int rin = wm * 32 + mt * 16 + lrow;
        int gr0 = mBase + rin, gr1 = gr0 + 8;
        int lab0 = labels[gr0], lab1 = labels[gr1];
#pragma unroll
        for (int nt = 0; nt < 8; nt++) {
            int col = nBase + wn * 64 + nt * 8 + lk;
            if (col == lab0)     g_labv[gr0] = acc[mt][nt][0];
            if (col + 1 == lab0) g_labv[gr0] = acc[mt][nt][1];
            if (col == lab1)     g_labv[gr1] = acc[mt][nt][2];
            if (col + 1 == lab1) g_labv[gr1] = acc[mt][nt][3];
        }
    }
}

// ---------------- merge loss partials: one warp per row ----------------
__global__ void loss_merge(const int* __restrict__ labels)
{
    int row  = (blockIdx.x * blockDim.x + threadIdx.x) >> 5;
    int lane = threadIdx.x & 31;
    if (row >= Mc) return;
    const float* pm = g_pmax + (size_t)row * NTILES;
    const float* ps = g_psum + (size_t)row * NTILES;
    float M = -3.4e38f;
    for (int i = lane; i < NTILES; i += 32) M = fmaxf(M, pm[i]);
#pragma unroll
    for (int o = 16; o > 0; o >>= 1) M = fmaxf(M, __shfl_xor_sync(0xffffffffu, M, o));
    float S = 0.f;
    for (int i = lane; i < NTILES; i += 32) S += ps[i] * __expf(pm[i] - M);
#pragma unroll
    for (int o = 16; o > 0; o >>= 1) S += __shfl_xor_sync(0xffffffffu, S, o);
    if (lane == 0) {
        int lab = labels[row];
        if (lab >= 0) {
            g_nll[row]   = (M + __logf(S)) - g_labv[row];
            g_valid[row] = 1.0f;
        } else {
            g_nll[row]   = 0.0f;
            g_valid[row] = 0.0f;
        }
    }
}

// ======================= Tensor-core attention (bf16 in-place score/P buffer, 2 CTAs/SM) =======================
#define AT_SQ    0
#define AT_SKV   2560
#define AT_SP    19968
#define AT_SINV  53248
#define AT_SMEM  53504

__global__ __launch_bounds__(256, 2)
void attn3_kernel(const bf16* __restrict__ qkv, bf16* __restrict__ ctx)
{
    extern __shared__ __align__(16) char sm[];
    uint16_t* sQ  = (uint16_t*)(sm + AT_SQ);
    uint16_t* sK  = (uint16_t*)(sm + AT_SKV);
    uint16_t* sVT = (uint16_t*)(sm + AT_SKV);
    bf16*     sSP = (bf16*)    (sm + AT_SP);
    float*    sInv= (float*)   (sm + AT_SINV);
    const uint32_t smb = smem_to_u32(sm);
    const uint32_t sQa = smb + AT_SQ;
    const uint32_t sKa = smb + AT_SKV;
    const uint32_t sVa = smb + AT_SKV;
    const uint32_t sPa = smb + AT_SP;

    const int t = threadIdx.x, lane = t & 31, w = t >> 5;
    const int q0 = blockIdx.x * 32;
    const int h  = blockIdx.y;
    const int b  = blockIdx.z;
    const int sp = g_sep[b];
    const int lrow = lane >> 2;
    const int lk   = 2 * (lane & 3);
    const int lane8 = lane & 7;
    const int Lmax = max(q0 + 31, sp);
    const int nch  = (Lmax >> 7) + 1;

    const bf16* qbase = qkv + (size_t)(b * Sc + q0) * QKVN + h * DHc;
    const bf16* kbase = qkv + (size_t)(b * Sc) * QKVN + Hc + h * DHc;
    const bf16* vbase = qkv + (size_t)(b * Sc) * QKVN + 2 * Hc + h * DHc;

    uint32_t aoffQ[2], aoffP[2];
#pragma unroll
    for (int mt = 0; mt < 2; mt++) {
        int arow = mt * 16 + ((lane >> 3) & 1) * 8 + lane8;
        int acol = (lane >> 4) * 8;
        aoffQ[mt] = (uint32_t)(arow * 40 + acol) * 2;
        aoffP[mt] = (uint32_t)(arow * 520 + acol) * 2;
    }
    const uint32_t boffK = (uint32_t)((w * 16 + ((lane >> 4) & 1) * 8 + lane8) * 40
                                      + ((lane >> 3) & 1) * 8) * 2;
    const uint32_t boffV = (uint32_t)((w * 8 + lane8) * 136 + ((lane >> 3) & 1) * 8) * 2;

#pragma unroll
    for (int i = 0; i < 2; i++) {
        int idx = t + i * 256;
        int r = idx >> 4, cg = idx & 15;
        uint2 v = *reinterpret_cast<const uint2*>(qbase + (size_t)r * QKVN + cg * 4);
        *reinterpret_cast<uint2*>(sQ + r * 40 + cg * 4) = v;
    }
    __syncthreads();

    for (int c = 0; c < nch; c++) {
        const int kb0 = c * 128;
#pragma unroll
        for (int i = 0; i < 8; i++) {
            int idx = t + i * 256;
            int r = idx >> 4, cg = idx & 15;
            uint2 v = *reinterpret_cast<const uint2*>(kbase + (size_t)(kb0 + r) * QKVN + cg * 4);
            *reinterpret_cast<uint2*>(sK + r * 40 + cg * 4) = v;
        }
        __syncthreads();

        float sacc[2][2][4];
#pragma unroll
        for (int mt = 0; mt < 2; mt++)
#pragma unroll
            for (int nt = 0; nt < 2; nt++)
#pragma unroll
                for (int i = 0; i < 4; i++) sacc[mt][nt][i] = 0.f;

#pragma unroll
        for (int ks = 0; ks < 4; ks++) {
            uint32_t af[2][4];
            ldmx4(af[0], sQa + aoffQ[0] + ks * 32);
            ldmx4(af[1], sQa + aoffQ[1] + ks * 32);
            uint32_t bf[4];
            ldmx4(bf, sKa + boffK + ks * 32);
            mma_bf16(sacc[0][0], af[0], bf[0], bf[1]);
            mma_bf16(sacc[1][0], af[1], bf[0], bf[1]);
            mma_bf16(sacc[0][1], af[0], bf[2], bf[3]);
            mma_bf16(sacc[1][1], af[1], bf[2], bf[3]);
        }
#pragma unroll
        for (int mt = 0; mt < 2; mt++) {
            const int r = mt * 16 + lrow;
#pragma unroll
            for (int nt = 0; nt < 2; nt++) {
                const int kcol = kb0 + w * 16 + nt * 8 + lk;
                bf162 lo, hi;
                lo.x = __float2bfloat16_rn(sacc[mt][nt][0] * 0.125f);
                lo.y = __float2bfloat16_rn(sacc[mt][nt][1] * 0.125f);
                hi.x = __float2bfloat16_rn(sacc[mt][nt][2] * 0.125f);
                hi.y = __float2bfloat16_rn(sacc[mt][nt][3] * 0.125f);
                *reinterpret_cast<bf162*>(sSP + r * 520 + kcol) = lo;
                *reinterpret_cast<bf162*>(sSP + (r + 8) * 520 + kcol) = hi;
            }
        }
        __syncthreads();
    }

    {
        const int r = t >> 3, sub = t & 7;
        const int Lk = max(q0 + r, sp);
        const int jmax = nch * 128;
        float m = -3.4e38f;
        for (int j = sub; j <= Lk; j += 8) m = fmaxf(m, __bfloat162float(sSP[r * 520 + j]));
#pragma unroll
        for (int msk = 1; msk < 8; msk <<= 1)
            m = fmaxf(m, __shfl_xor_sync(0xffffffffu, m, msk));
        float sum = 0.f;
        for (int j = sub; j < jmax; j += 8) {
            if (j <= Lk) {
                float e = __expf(__bfloat162float(sSP[r * 520 + j]) - m);
                sSP[r * 520 + j] = __float2bfloat16_rn(e);
                sum += e;
            } else {
                sSP[r * 520 + j] = __float2bfloat16_rn(0.f);
            }
        }
#pragma unroll
        for (int msk = 1; msk < 8; msk <<= 1)
            sum += __shfl_xor_sync(0xffffffffu, sum, msk);
        if (sub == 0) sInv[r] = 1.0f / sum;
    }
    __syncthreads();

    float cacc[2][4];
#pragma unroll
    for (int mt = 0; mt < 2; mt++)
#pragma unroll
        for (int i = 0; i < 4; i++) cacc[mt][i] = 0.f;

    for (int c = 0; c < nch; c++) {
        const int kb0 = c * 128;
#pragma unroll
        for (int i = 0; i < 8; i++) {
            int idx = t + i * 256;
            int kpos = idx >> 4, dg = idx & 15;
            uint2 v = *reinterpret_cast<const uint2*>(vbase + (size_t)(kb0 + kpos) * QKVN + dg * 4);
            sVT[(dg * 4 + 0) * 136 + kpos] = (uint16_t)(v.x);
            sVT[(dg * 4 + 1) * 136 + kpos] = (uint16_t)(v.x >> 16);
            sVT[(dg * 4 + 2) * 136 + kpos] = (uint16_t)(v.y);
            sVT[(dg * 4 + 3) * 136 + kpos] = (uint16_t)(v.y >> 16);
        }
        __syncthreads();
#pragma unroll
        for (int ks = 0; ks < 8; ks++) {
            uint32_t af[2][4];
            ldmx4(af[0], sPa + aoffP[0] + (kb0 + ks * 16) * 2);
            ldmx4(af[1], sPa + aoffP[1] + (kb0 + ks * 16) * 2);
            uint32_t bv[2];
            ldmx2(bv, sVa + boffV + ks * 32);
            mma_bf16(cacc[0], af[0], bv[0], bv[1]);
            mma_bf16(cacc[1], af[1], bv[0], bv[1]);
        }
        __syncthreads();
    }
#pragma unroll
    for (int mt = 0; mt < 2; mt++) {
        const int r = mt * 16 + lrow;
        const float inv0 = sInv[r], inv1 = sInv[r + 8];
        const int d0 = w * 8 + lk;
        bf162 lo, hi;
        lo.x = __float2bfloat16_rn(cacc[mt][0] * inv0);
        lo.y = __float2bfloat16_rn(cacc[mt][1] * inv0);
        hi.x = __float2bfloat16_rn(cacc[mt][2] * inv1);
        hi.y = __float2bfloat16_rn(cacc[mt][3] * inv1);
        *reinterpret_cast<bf162*>(ctx + (size_t)(b * Sc + q0 + r)     * Hc + h * DHc + d0) = lo;
        *reinterpret_cast<bf162*>(ctx + (size_t)(b * Sc + q0 + r + 8) * Hc + h * DHc + d0) = hi;
    }
}

// ---------------- Deterministic final reduction ----------------
__global__ void loss_reduce_kernel(float* __restrict__ out)
{
    __shared__ float rs[1024];
    __shared__ float rc[1024];
    int tid = threadIdx.x;
    float s = 0.f, c = 0.f;
    for (int i = tid; i < Mc; i += 1024) { s += g_nll[i]; c += g_valid[i]; }
    rs[tid] = s; rc[tid] = c; __syncthreads();
    for (int o = 512; o > 0; o >>= 1) {
        if (tid < o) { rs[tid] += rs[tid+o]; rc[tid] += rc[tid+o]; }
        __syncthreads();
    }
    if (tid == 0) out[0] = rs[0] / fmaxf(rc[0], 1.0f);
}

// ---------------- Host orchestration ----------------
static void run_tr_b(const float* in, bf16* out, int K, int N,
                     size_t inStride, size_t outStride, int layers)
{
    dim3 g((N + 31) / 32, (K + 63) / 64, layers);
    transpose_bf16_b<<<g, dim3(32, 8)>>>(in, out, K, N, inStride, outStride);
}

template<int ACT, int OUTBF>
static void run_gemm_t(const bf16* A, const bf16* Bt, const float* bias, void* C,
                       int M, int N, int K)
{
    dim3 grid((N + 127) / 128, M / 128);
    tc_gemm<ACT, OUTBF><<<grid, 256, GEMM_SMEM_BYTES>>>(A, Bt, bias, C, M, N, K);
}

extern "C" void kernel_launch(void* const* d_in, const int* in_sizes, int n_in,
                              void* d_out, int out_size)
{
    (void)in_sizes; (void)n_in; (void)out_size;

    const int*   ids      = (const int*)  d_in[0];
    const int*   labels   = (const int*)  d_in[1];
    const float* word_emb = (const float*)d_in[2];
    const float* pos_emb  = (const float*)d_in[3];
    const float* type_emb = (const float*)d_in[4];
    const float* eg       = (const float*)d_in[5];
    const float* eb       = (const float*)d_in[6];
    const float* Wq       = (const float*)d_in[7];
    const float* bq       = (const float*)d_in[8];
    const float* Wk       = (const float*)d_in[9];
    const float* bk       = (const float*)d_in[10];
    const float* Wv       = (const float*)d_in[11];
    const float* bv       = (const float*)d_in[12];
    const float* Wo       = (const float*)d_in[13];
    const float* bo       = (const float*)d_in[14];
    const float* l1g      = (const float*)d_in[15];
    const float* l1b      = (const float*)d_in[16];
    const float* Wi       = (const float*)d_in[17];
    const float* bi       = (const float*)d_in[18];
    const float* Wd       = (const float*)d_in[19];
    const float* bd       = (const float*)d_in[20];
    const float* l2g      = (const float*)d_in[21];
    const float* l2b      = (const float*)d_in[22];
    const float* Wc       = (const float*)d_in[23];
    const float* bc       = (const float*)d_in[24];

    // SMEM opt-ins for every kernel above the 48KB default
    cudaFuncSetAttribute(attn3_kernel,  cudaFuncAttributeMaxDynamicSharedMemorySize, AT_SMEM);
    cudaFuncSetAttribute(tc_gemm<0,0>,  cudaFuncAttributeMaxDynamicSharedMemorySize, GEMM_SMEM_BYTES);
    cudaFuncSetAttribute(tc_gemm<0,1>,  cudaFuncAttributeMaxDynamicSharedMemorySize, GEMM_SMEM_BYTES);
    cudaFuncSetAttribute(tc_gemm<1,1>,  cudaFuncAttributeMaxDynamicSharedMemorySize, GEMM_SMEM_BYTES);
    cudaFuncSetAttribute(tc_gemm_loss,  cudaFuncAttributeMaxDynamicSharedMemorySize, GEMM_SMEM_BYTES);

    void* p;
    cudaGetSymbolAddress(&p, g_x);      float* px    = (float*)p;
    cudaGetSymbolAddress(&p, g_xb);     bf16*  pxb   = (bf16*)p;
    cudaGetSymbolAddress(&p, g_qkvb);   bf16*  pqkvb = (bf16*)p;
    cudaGetSymbolAddress(&p, g_ctxb);   bf16*  pctxb = (bf16*)p;
    cudaGetSymbolAddress(&p, g_proj);   float* pproj = (float*)p;
    cudaGetSymbolAddress(&p, g_ffnb);   bf16*  pffnb = (bf16*)p;
    cudaGetSymbolAddress(&p, g_bqkv);   float* pbqkv = (float*)p;
    cudaGetSymbolAddress(&p, g_WqkvT);  bf16*  pWqkvT= (bf16*)p;
    cudaGetSymbolAddress(&p, g_WoT);    bf16*  pWoT  = (bf16*)p;
    cudaGetSymbolAddress(&p, g_WiT);    bf16*  pWiT  = (bf16*)p;
    cudaGetSymbolAddress(&p, g_WdT);    bf16*  pWdT  = (bf16*)p;
    cudaGetSymbolAddress(&p, g_WcT);    bf16*  pWcT  = (bf16*)p;

    // Batched weight transposes (7 launches)
    const size_t HH = (size_t)Hc * Hc;
    run_tr_b(Wq, pWqkvT,                    Hc, Hc, HH, (size_t)QKVN*Hc, Lc);
    run_tr_b(Wk, pWqkvT + HH,               Hc, Hc, HH, (size_t)QKVN*Hc, Lc);
    run_tr_b(Wv, pWqkvT + 2*HH,             Hc, Hc, HH, (size_t)QKVN*Hc, Lc);
    run_tr_b(Wo, pWoT,                      Hc, Hc, HH, HH, Lc);
    run_tr_b(Wi, pWiT,  Hc, FFc, (size_t)Hc*FFc, (size_t)FFc*Hc, Lc);
    run_tr_b(Wd, pWdT,  FFc, Hc, (size_t)FFc*Hc, (size_t)Hc*FFc, Lc);
    run_tr_b(Wc, pWcT,  Hc, Vc,  0, 0, 1);

    build_qkv_bias<<<(Lc*QKVN + 255)/256, 256>>>(bq, bk, bv);
    sep_kernel<<<1, 32>>>(ids);
    embed_ln_kernel<<<Mc, 256>>>(ids, word_emb, pos_emb, type_emb, eg, eb);

    for (int l = 0; l < Lc; l++) {
        run_gemm_t<0,1>(pxb, pWqkvT + (size_t)l*QKVN*Hc, pbqkv + (size_t)l*QKVN,
                        pqkvb, Mc, QKVN, Hc);
        attn3_kernel<<<dim3(Sc/32, NHc, Bc), 256, AT_SMEM>>>(pqkvb, pctxb);
        run_gemm_t<0,0>(pctxb, pWoT + (size_t)l*HH, bo + (size_t)l*Hc, pproj, Mc, Hc, Hc);
        add_ln_kernel<<<Mc, 256>>>(px, pxb, pproj, l1g + (size_t)l*Hc, l1b + (size_t)l*Hc);
        run_gemm_t<1,1>(pxb, pWiT + (size_t)l*FFc*Hc, bi + (size_t)l*FFc, pffnb, Mc, FFc, Hc);
        run_gemm_t<0,0>(pffnb, pWdT + (size_t)l*Hc*FFc, bd + (size_t)l*Hc, pproj, Mc, Hc, FFc);
        add_ln_kernel<<<Mc, 256>>>(px, pxb, pproj, l2g + (size_t)l*Hc, l2b + (size_t)l*Hc);
    }

    // classifier + fused loss
    {
        dim3 grid(NTILES, Mc / 128);
        tc_gemm_loss<<<grid, 256, GEMM_SMEM_BYTES>>>(pxb, pWcT, bc, labels, Mc, Vc, Hc);
    }
    loss_merge<<<(Mc * 32 + 255) / 256, 256>>>(labels);
    loss_reduce_kernel<<<1, 1024>>>((float*)d_out);
}

// round 16
// speedup vs baseline: 1.0713x; 1.0333x over previous
#include <cuda_runtime.h>
#include <cuda_bf16.h>
#include <math.h>
#include <stdint.h>

// Problem constants
#define Lc 12
#define Hc 768
#define NHc 12
#define DHc 64
#define FFc 3072
#define Vc 21128
#define Sc 512
#define Bc 8
#define Mc (Bc*Sc)          // 4096 tokens
#define SEPc 102
#define LN_EPS 1e-12f
#define QKVN 2304
#define NTILES 166          // ceil(Vc/128)

typedef __nv_bfloat16 bf16;
typedef __nv_bfloat162 bf162;

// ---------------- Device scratch (static; no runtime allocation) ----------------
__device__ float g_x[Mc*Hc];               // fp32 residual stream
__device__ bf16  g_xb[Mc*Hc];              // bf16 copy of x (GEMM A operand)
__device__ bf16  g_qkvb[(size_t)Mc*QKVN];  // fused QKV output (bf16)
__device__ bf16  g_ctxb[Mc*Hc];            // attention output (bf16, feeds Wo)
__device__ float g_proj[Mc*Hc];            // fp32 GEMM output before residual+LN
__device__ bf16  g_ffnb[(size_t)Mc*FFc];   // GELU output (bf16, feeds Wd)
__device__ float g_pmax[(size_t)Mc*NTILES];
__device__ float g_psum[(size_t)Mc*NTILES];
__device__ float g_labv[Mc];
__device__ float g_nll[Mc];
__device__ float g_valid[Mc];
__device__ int   g_sep[Bc];
__device__ float g_bqkv[Lc*QKVN];          // fused QKV bias
// Transposed (N-major, K-contiguous) bf16 weights
__device__ bf16 g_WqkvT[(size_t)Lc*QKVN*Hc];
__device__ bf16 g_WoT[Lc*Hc*Hc];
__device__ bf16 g_WiT[(size_t)Lc*FFc*Hc];
__device__ bf16 g_WdT[(size_t)Lc*Hc*FFc];
__device__ bf16 g_WcT[(size_t)Vc*Hc];

// ---------------- small PTX helpers (compute_103-safe) ----------------
__device__ __forceinline__ uint32_t smem_to_u32(const void* smem_ptr) {
    uint32_t addr;
    asm("{ .reg .u64 tmp; cvta.to.shared.u64 tmp, %1; cvt.u32.u64 %0, tmp; }"
        : "=r"(addr) : "l"(smem_ptr));
    return addr;
}
__device__ __forceinline__ void cp16(uint32_t dst, const void* src, bool pred) {
    uint32_t sz = pred ? 16u : 0u;
    asm volatile("cp.async.cg.shared.global [%0], [%1], 16, %2;"
                 :: "r"(dst), "l"(src), "r"(sz));
}
#define CP_COMMIT() asm volatile("cp.async.commit_group;" ::: "memory")
#define CP_WAIT0()  asm volatile("cp.async.wait_group 0;" ::: "memory")
#define CP_WAIT1()  asm volatile("cp.async.wait_group 1;" ::: "memory")

__device__ __forceinline__ void mma_bf16(float* c, const uint32_t* a,
                                         uint32_t b0, uint32_t b1) {
    asm volatile(
        "mma.sync.aligned.m16n8k16.row.col.f32.bf16.bf16.f32 "
        "{%0,%1,%2,%3}, {%4,%5,%6,%7}, {%8,%9}, {%0,%1,%2,%3};"
        : "+f"(c[0]), "+f"(c[1]), "+f"(c[2]), "+f"(c[3])
        : "r"(a[0]), "r"(a[1]), "r"(a[2]), "r"(a[3]), "r"(b0), "r"(b1));
}
__device__ __forceinline__ void ldmx4(uint32_t* r, uint32_t addr) {
    asm volatile("ldmatrix.sync.aligned.m8n8.x4.shared.b16 {%0,%1,%2,%3}, [%4];"
        : "=r"(r[0]), "=r"(r[1]), "=r"(r[2]), "=r"(r[3]) : "r"(addr));
}
__device__ __forceinline__ void ldmx2(uint32_t* r, uint32_t addr) {
    asm volatile("ldmatrix.sync.aligned.m8n8.x2.shared.b16 {%0,%1}, [%2];"
        : "=r"(r[0]), "=r"(r[1]) : "r"(addr));
}

__device__ __forceinline__ float gelu_exact(float v) {
    return 0.5f * v * (1.0f + erff(v * 0.70710678118654752f));
}

// ---------------- Batched weight transpose + bf16 conversion (bf162 stores) ----------------
__global__ void transpose_bf16_b(const float* __restrict__ in, bf16* __restrict__ out,
                                 int K, int N, size_t inStride, size_t outStride)
{
    __shared__ float tile[64][33];
    in  += (size_t)blockIdx.z * inStride;
    out += (size_t)blockIdx.z * outStride;
    int kb = blockIdx.y * 64, nb = blockIdx.x * 32;
    int tx = threadIdx.x, ty = threadIdx.y;
    for (int i = ty; i < 64; i += 8) {
        int kk = kb + i, nn = nb + tx;
        tile[i][tx] = (kk < K && nn < N) ? in[(size_t)kk * N + nn] : 0.0f;
    }
    __syncthreads();
    for (int i = ty; i < 32; i += 8) {
        int nn = nb + i;
        int kk = kb + 2 * tx;
        if (nn < N && kk < K) {
            bf162 o;
            o.x = __float2bfloat16_rn(tile[2*tx][i]);
            o.y = __float2bfloat16_rn(tile[2*tx + 1][i]);
            *reinterpret_cast<bf162*>(out + (size_t)nn * K + kk) = o;
        }
    }
}

// ---------------- fused QKV bias ----------------
__global__ void build_qkv_bias(const float* __restrict__ bq, const float* __restrict__ bk,
                               const float* __restrict__ bv)
{
    int i = blockIdx.x * 256 + threadIdx.x;
    if (i < Lc * QKVN) {
        int l = i / QKVN, c = i % QKVN;
        float v;
        if (c < Hc)            v = bq[l*Hc + c];
        else if (c < 2*Hc)     v = bk[l*Hc + c - Hc];
        else                   v = bv[l*Hc + c - 2*Hc];
        g_bqkv[i] = v;
    }
}

// ---------------- [SEP] position per batch row ----------------
__global__ void sep_kernel(const int* __restrict__ ids) {
    int b = threadIdx.x;
    if (b < Bc) {
        int s = Sc - 1;
        for (int i = 0; i < Sc; i++) {
            if (ids[b*Sc + i] == SEPc) { s = i; break; }
        }
        g_sep[b] = s;
    }
}

// ---------------- Embedding + LayerNorm (dual fp32 + bf16 output) ----------------
__global__ void embed_ln_kernel(const int* __restrict__ ids,
                                const float* __restrict__ we,
                                const float* __restrict__ pe,
                                const float* __restrict__ te,
                                const float* __restrict__ gg,
                                const float* __restrict__ bb)
{
    int row = blockIdx.x;
    int s   = row % Sc;
    int tid = threadIdx.x;
    __shared__ float buf[Hc];
    __shared__ float wsum[8], wsq[8];
    int id = ids[row];
    float lsum = 0.f, lsq = 0.f;
    for (int j = tid; j < Hc; j += 256) {
        float val = we[(size_t)id*Hc + j] + pe[s*Hc + j] + te[j];
        buf[j] = val;
        lsum += val; lsq += val * val;
    }
#pragma unroll
    for (int o = 16; o > 0; o >>= 1) {
        lsum += __shfl_xor_sync(0xffffffffu, lsum, o);
        lsq  += __shfl_xor_sync(0xffffffffu, lsq,  o);
    }
    if ((tid & 31) == 0) { wsum[tid >> 5] = lsum; wsq[tid >> 5] = lsq; }
    __syncthreads();
    float ts = 0.f, tq = 0.f;
#pragma unroll
    for (int i = 0; i < 8; i++) { ts += wsum[i]; tq += wsq[i]; }
    float mean = ts * (1.0f/Hc);
    float var  = fmaxf(tq * (1.0f/Hc) - mean * mean, 0.f);
    float inv  = rsqrtf(var + LN_EPS);
    for (int j = tid; j < Hc; j += 256) {
        float o = (buf[j]-mean)*inv*gg[j] + bb[j];
        g_x[(size_t)row*Hc + j]  = o;
        g_xb[(size_t)row*Hc + j] = __float2bfloat16_rn(o);
    }
}

// ---------------- Residual add + LayerNorm, dual output ----------------
__global__ void add_ln_kernel(float* __restrict__ x, bf16* __restrict__ xb,
                              const float* __restrict__ t,
                              const float* __restrict__ gg, const float* __restrict__ bb)
{
    int row = blockIdx.x;
    int tid = threadIdx.x;
    __shared__ float buf[Hc];
    __shared__ float wsum[8], wsq[8];
    float lsum = 0.f, lsq = 0.f;
    for (int j = tid; j < Hc; j += 256) {
        float val = x[(size_t)row*Hc + j] + t[(size_t)row*Hc + j];
        buf[j] = val;
        lsum += val; lsq += val * val;
    }
#pragma unroll
    for (int o = 16; o > 0; o >>= 1) {
        lsum += __shfl_xor_sync(0xffffffffu, lsum, o);
        lsq  += __shfl_xor_sync(0xffffffffu, lsq,  o);
    }
    if ((tid & 31) == 0) { wsum[tid >> 5] = lsum; wsq[tid >> 5] = lsq; }
    __syncthreads();
    float ts = 0.f, tq = 0.f;
#pragma unroll
    for (int i = 0; i < 8; i++) { ts += wsum[i]; tq += wsq[i]; }
    float mean = ts * (1.0f/Hc);
    float var  = fmaxf(tq * (1.0f/Hc) - mean * mean, 0.f);
    float inv  = rsqrtf(var + LN_EPS);
    for (int j = tid; j < Hc; j += 256) {
        float o = (buf[j]-mean)*inv*gg[j] + bb[j];
        x[(size_t)row*Hc + j]  = o;
        xb[(size_t)row*Hc + j] = __float2bfloat16_rn(o);
    }
}

// ======================= mma.sync bf16 GEMM (3-stage pipeline + ldmatrix, 2 CTAs/SM) =======================
#define STG_HW 5120            // halfwords per stage (128*40)
#define STG_B  10240           // bytes per stage
#define GEMM_SMEM_BYTES 61440  // 6 buffers (A0-2, B0-2)

template<int ACT, int OUTBF>
__global__ __launch_bounds__(256, 2)
void tc_gemm(const bf16* __restrict__ A, const bf16* __restrict__ Bt,
             const float* __restrict__ bias, void* __restrict__ Cv,
             int M, int N, int K)
{
    extern __shared__ __align__(16) char smraw[];
    const uint32_t sbase = smem_to_u32(smraw);

    const int t    = threadIdx.x;
    const int lane = t & 31;
    const int w    = t >> 5;
    const int wm   = w & 3;
    const int wn   = w >> 2;
    const int m0   = blockIdx.y * 128;
    const int n0   = blockIdx.x * 128;
    const int nk   = K >> 5;

    float acc[2][8][4];
#pragma unroll
    for (int mt = 0; mt < 2; mt++)
#pragma unroll
        for (int nt = 0; nt < 8; nt++)
#pragma unroll
            for (int i = 0; i < 4; i++) acc[mt][nt][i] = 0.f;

    auto load_stage = [&](int c) {
        const int s  = c % 3;
        const int k0 = c << 5;
        const uint32_t aB = sbase + (uint32_t)s * STG_B;
        const uint32_t bB = sbase + 3u * STG_B + (uint32_t)s * STG_B;
#pragma unroll
        for (int i = 0; i < 2; i++) {
            int idx = t + i * 256;
            int row = idx >> 2, q = idx & 3;
            cp16(aB + (uint32_t)(row * 80 + q * 16),
                 A + (size_t)(m0 + row) * K + k0 + q * 8, true);
            int nr = n0 + row;
            bool p = nr < N;
            int nrc = p ? nr : 0;
            cp16(bB + (uint32_t)(row * 80 + q * 16),
                 Bt + (size_t)nrc * K + k0 + q * 8, p);
        }
        CP_COMMIT();
    };

    const int lane8 = lane & 7;
    uint32_t aoffB[2], boffB[4];
#pragma unroll
    for (int mt = 0; mt < 2; mt++) {
        int arow = wm * 32 + mt * 16 + ((lane >> 3) & 1) * 8 + lane8;
        int acol = (lane >> 4) * 8;
        aoffB[mt] = (uint32_t)(arow * 40 + acol) * 2;
    }
#pragma unroll
    for (int jp = 0; jp < 4; jp++) {
        int brow = wn * 64 + jp * 16 + ((lane >> 4) & 1) * 8 + lane8;
        int bcol = ((lane >> 3) & 1) * 8;
        boffB[jp] = (uint32_t)(brow * 40 + bcol) * 2;
    }

    load_stage(0);
    if (nk > 1) load_stage(1);
    for (int c = 0; c < nk; c++) {
        if (c + 1 < nk) { CP_WAIT1(); } else { CP_WAIT0(); }
        __syncthreads();
        if (c + 2 < nk) load_stage(c + 2);

        const int s = c % 3;
        const uint32_t aStage = sbase + (uint32_t)s * STG_B;
        const uint32_t bStage = sbase + 3u * STG_B + (uint32_t)s * STG_B;
#pragma unroll
        for (int ks = 0; ks < 2; ks++) {
            uint32_t af[2][4];
            ldmx4(af[0], aStage + aoffB[0] + ks * 32);
            ldmx4(af[1], aStage + aoffB[1] + ks * 32);
#pragma unroll
            for (int jp = 0; jp < 4; jp++) {
                uint32_t bf[4];
                ldmx4(bf, bStage + boffB[jp] + ks * 32);
                mma_bf16(acc[0][2*jp],     af[0], bf[0], bf[1]);
                mma_bf16(acc[1][2*jp],     af[1], bf[0], bf[1]);
                mma_bf16(acc[0][2*jp + 1], af[0], bf[2], bf[3]);
                mma_bf16(acc[1][2*jp + 1], af[1], bf[2], bf[3]);
            }
        }
    }

    const int lrow = lane >> 2;
    const int lk   = 2 * (lane & 3);
    float* Cf = (float*)Cv;
    bf16*  Cb = (bf16*)Cv;
#pragma unroll
    for (int mt = 0; mt < 2; mt++) {
        int rlo = m0 + wm * 32 + mt * 16 + lrow;
        int rhi = rlo + 8;
#pragma unroll
        for (int nt = 0; nt < 8; nt++) {
            int col = n0 + wn * 64 + nt * 8 + lk;
            if (col < N) {
                float b0v = bias[col], b1v = bias[col + 1];
                float v0 = acc[mt][nt][0] + b0v;
                float v1 = acc[mt][nt][1] + b1v;
                float v2 = acc[mt][nt][2] + b0v;
                float v3 = acc[mt][nt][3] + b1v;
                if (ACT == 1) {
                    v0 = gelu_exact(v0); v1 = gelu_exact(v1);
                    v2 = gelu_exact(v2); v3 = gelu_exact(v3);
                }
                if (OUTBF) {
                    bf162 lo; lo.x = __float2bfloat16_rn(v0); lo.y = __float2bfloat16_rn(v1);
                    bf162 hi; hi.x = __float2bfloat16_rn(v2); hi.y = __float2bfloat16_rn(v3);
                    *reinterpret_cast<bf162*>(Cb + (size_t)rlo * N + col) = lo;
                    *reinterpret_cast<bf162*>(Cb + (size_t)rhi * N + col) = hi;
                } else {
                    float2 lo; lo.x = v0; lo.y = v1;
                    float2 hi; hi.x = v2; hi.y = v3;
                    *reinterpret_cast<float2*>(Cf + (size_t)rlo * N + col) = lo;
                    *reinterpret_cast<float2*>(Cf + (size_t)rhi * N + col) = hi;
                }
            }
        }
    }
}

// ======================= 64-row-M-tile GEMM (for N=768 GEMMs; better wave balance) =======================
// CTA tile 64x128; 8 warps as 2(M) x 4(N), warp tile 32x32. 3 CTAs/SM.
#define STG64_A_B 5120         // 64*40 hw * 2B
#define GEMM64_SMEM (3*STG64_A_B + 3*STG_B)   // 46080

template<int ACT, int OUTBF>
__global__ __launch_bounds__(256, 3)
void tc_gemm64(const bf16* __restrict__ A, const bf16* __restrict__ Bt,
               const float* __restrict__ bias, void* __restrict__ Cv,
               int M, int N, int K)
{
    extern __shared__ __align__(16) char smraw[];
    const uint32_t sbase = smem_to_u32(smraw);

    const int t    = threadIdx.x;
    const int lane = t & 31;
    const int w    = t >> 5;
    const int wm   = w & 1;      // 0..1 (M)
    const int wn   = w >> 1;     // 0..3 (N)
    const int m0   = blockIdx.y * 64;
    const int n0   = blockIdx.x * 128;
    const int nk   = K >> 5;

    float acc[2][4][4];
#pragma unroll
    for (int mt = 0; mt < 2; mt++)
#pragma unroll
        for (int nt = 0; nt < 4; nt++)
#pragma unroll
            for (int i = 0; i < 4; i++) acc[mt][nt][i] = 0.f;

    auto load_stage = [&](int c) {
        const int s  = c % 3;
        const int k0 = c << 5;
        const uint32_t aB = sbase + (uint32_t)s * STG64_A_B;
        const uint32_t bB = sbase + 3u * STG64_A_B + (uint32_t)s * STG_B;
        {   // A: 64 rows x 4 chunks = 256 cp16, 1 per thread
            int row = t >> 2, q = t & 3;
            cp16(aB + (uint32_t)(row * 80 + q * 16),
                 A + (size_t)(m0 + row) * K + k0 + q * 8, true);
        }
#pragma unroll
        for (int i = 0; i < 2; i++) {   // B: 128 rows x 4 chunks = 512 cp16
            int idx = t + i * 256;
            int row = idx >> 2, q = idx & 3;
            int nr = n0 + row;
            bool p = nr < N;
            int nrc = p ? nr : 0;
            cp16(bB + (uint32_t)(row * 80 + q * 16),
                 Bt + (size_t)nrc * K + k0 + q * 8, p);
        }
        CP_COMMIT();
    };

    const int lane8 = lane & 7;
    uint32_t aoffB[2], boffB[2];
#pragma unroll
    for (int mt = 0; mt < 2; mt++) {
        int arow = wm * 32 + mt * 16 + ((lane >> 3) & 1) * 8 + lane8;
        int acol = (lane >> 4) * 8;
        aoffB[mt] = (uint32_t)(arow * 40 + acol) * 2;
    }
#pragma unroll
    for (int jp = 0; jp < 2; jp++) {
        int brow = wn * 32 + jp * 16 + ((lane >> 4) & 1) * 8 + lane8;
        int bcol = ((lane >> 3) & 1) * 8;
        boffB[jp] = (uint32_t)(brow * 40 + bcol) * 2;
    }

    load_stage(0);
    if (nk > 1) load_stage(1);
    for (int c = 0; c < nk; c++) {
        if (c + 1 < nk) { CP_WAIT1(); } else { CP_WAIT0(); }
        __syncthreads();
        if (c + 2 < nk) load_stage(c + 2);

        const int s = c % 3;
        const uint32_t aStage = sbase + (uint32_t)s * STG64_A_B;
        const uint32_t bStage = sbase + 3u * STG64_A_B + (uint32_t)s * STG_B;
#pragma unroll
        for (int ks = 0; ks < 2; ks++) {
            uint32_t af[2][4];
            ldmx4(af[0], aStage + aoffB[0] + ks * 32);
            ldmx4(af[1], aStage + aoffB[1] + ks * 32);
#pragma unroll
            for (int jp = 0; jp < 2; jp++) {
                uint32_t bf[4];
                ldmx4(bf, bStage + boffB[jp] + ks * 32);
                mma_bf16(acc[0][2*jp],     af[0], bf[0], bf[1]);
                mma_bf16(acc[1][2*jp],     af[1], bf[0], bf[1]);
                mma_bf16(acc[0][2*jp + 1], af[0], bf[2], bf[3]);
                mma_bf16(acc[1][2*jp + 1], af[1], bf[2], bf[3]);
            }
        }
    }

    const int lrow = lane >> 2;
    const int lk   = 2 * (lane & 3);
    float* Cf = (float*)Cv;
    bf16*  Cb = (bf16*)Cv;
#pragma unroll
    for (int mt = 0; mt < 2; mt++) {
        int rlo = m0 + wm * 32 + mt * 16 + lrow;
        int rhi = rlo + 8;
#pragma unroll
        for (int nt = 0; nt < 4; nt++) {
            int col = n0 + wn * 32 + nt * 8 + lk;
            if (col < N) {
                float b0v = bias[col], b1v = bias[col + 1];
                float v0 = acc[mt][nt][0] + b0v;
                float v1 = acc[mt][nt][1] + b1v;
                float v2 = acc[mt][nt][2] + b0v;
                float v3 = acc[mt][nt][3] + b1v;
                if (ACT == 1) {
                    v0 = gelu_exact(v0); v1 = gelu_exact(v1);
                    v2 = gelu_exact(v2); v3 = gelu_exact(v3);
                }
                if (OUTBF) {
                    bf162 lo; lo.x = __float2bfloat16_rn(v0); lo.y = __float2bfloat16_rn(v1);
                    bf162 hi; hi.x = __float2bfloat16_rn(v2); hi.y = __float2bfloat16_rn(v3);
                    *reinterpret_cast<bf162*>(Cb + (size_t)rlo * N + col) = lo;
                    *reinterpret_cast<bf162*>(Cb + (size_t)rhi * N + col) = hi;
                } else {
                    float2 lo; lo.x = v0; lo.y = v1;
                    float2 hi; hi.x = v2; hi.y = v3;
                    *reinterpret_cast<float2*>(Cf + (size_t)rlo * N + col) = lo;
                    *reinterpret_cast<float2*>(Cf + (size_t)rhi * N + col) = hi;
                }
            }
        }
    }
}

// ======================= Classifier GEMM + fused log-softmax partials =======================
__global__ __launch_bounds__(256, 2)
void tc_gemm_loss(const bf16* __restrict__ A, const bf16* __restrict__ Bt,
                  const float* __restrict__ bias, const int* __restrict__ labels,
                  int M, int N, int K)
{
    extern __shared__ __align__(16) char smraw[];
    const uint32_t sbase = smem_to_u32(smraw);
    __shared__ float sMx[128][2];
    __shared__ float sSm[128][2];

    const int t    = threadIdx.x;
    const int lane = t & 31;
    const int w    = t >> 5;
    const int wm   = w & 3;
    const int wn   = w >> 2;
    const int mBase = blockIdx.y * 128;
    const int nBase = blockIdx.x * 128;
    const int nk   = K >> 5;

    float acc[2][8][4];
#pragma unroll
    for (int mt = 0; mt < 2; mt++)
#pragma unroll
        for (int nt = 0; nt < 8; nt++)
#pragma unroll
            for (int i = 0; i < 4; i++) acc[mt][nt][i] = 0.f;

    auto load_stage = [&](int c) {
        const int s  = c % 3;
        const int k0 = c << 5;
        const uint32_t aB = sbase + (uint32_t)s * STG_B;
        const uint32_t bB = sbase + 3u * STG_B + (uint32_t)s * STG_B;
#pragma unroll
        for (int i = 0; i < 2; i++) {
            int idx = t + i * 256;
            int row = idx >> 2, q = idx & 3;
            cp16(aB + (uint32_t)(row * 80 + q * 16),
                 A + (size_t)(mBase + row) * K + k0 + q * 8, true);
            int nr = nBase + row;
            bool p = nr < N;
            int nrc = p ? nr : 0;
            cp16(bB + (uint32_t)(row * 80 + q * 16),
                 Bt + (size_t)nrc * K + k0 + q * 8, p);
        }
        CP_COMMIT();
    };

    const int lane8 = lane & 7;
    uint32_t aoffB[2], boffB[4];
#pragma unroll
    for (int mt = 0; mt < 2; mt++) {
        int arow = wm * 32 + mt * 16 + ((lane >> 3) & 1) * 8 + lane8;
        int acol = (lane >> 4) * 8;
        aoffB[mt] = (uint32_t)(arow * 40 + acol) * 2;
    }
#pragma unroll
    for (int jp = 0; jp < 4; jp++) {
        int brow = wn * 64 + jp * 16 + ((lane >> 4) & 1) * 8 + lane8;
        int bcol = ((lane >> 3) & 1) * 8;
        boffB[jp] = (uint32_t)(brow * 40 + bcol) * 2;
    }

    const int lrow = lane >> 2;
    const int lk   = 2 * (lane & 3);

    load_stage(0);
    if (nk > 1) load_stage(1);
    for (int c = 0; c < nk; c++) {
        if (c + 1 < nk) { CP_WAIT1(); } else { CP_WAIT0(); }
        __syncthreads();
        if (c + 2 < nk) load_stage(c + 2);

        const int s = c % 3;
        const uint32_t aStage = sbase + (uint32_t)s * STG_B;
        const uint32_t bStage = sbase + 3u * STG_B + (uint32_t)s * STG_B;
#pragma unroll
        for (int ks = 0; ks < 2; ks++) {
            uint32_t af[2][4];
            ldmx4(af[0], aStage + aoffB[0] + ks * 32);
            ldmx4(af[1], aStage + aoffB[1] + ks * 32);
#pragma unroll
            for (int jp = 0; jp < 4; jp++) {
                uint32_t bf[4];
                ldmx4(bf, bStage + boffB[jp] + ks * 32);
                mma_bf16(acc[0][2*jp],     af[0], bf[0], bf[1]);
                mma_bf16(acc[1][2*jp],     af[1], bf[0], bf[1]);
                mma_bf16(acc[0][2*jp + 1], af[0], bf[2], bf[3]);
                mma_bf16(acc[1][2*jp + 1], af[1], bf[2], bf[3]);
            }
        }
    }
    __syncthreads();

    // ---- loss epilogue ----
    float vmax[2][2];
#pragma unroll
    for (int mt = 0; mt < 2; mt++) { vmax[mt][0] = -3.4e38f; vmax[mt][1] = -3.4e38f; }
#pragma unroll
    for (int mt = 0; mt < 2; mt++)
#pragma unroll
        for (int nt = 0; nt < 8; nt++) {
            int col = nBase + wn * 64 + nt * 8 + lk;
            float b0v = (col     < N) ? bias[col]     : 0.f;
            float b1v = (col + 1 < N) ? bias[col + 1] : 0.f;
            float v0 = (col     < N) ? acc[mt][nt][0] + b0v : -3.4e38f;
            float v1 = (col + 1 < N) ? acc[mt][nt][1] + b1v : -3.4e38f;
            float v2 = (col     < N) ? acc[mt][nt][2] + b0v : -3.4e38f;
            float v3 = (col + 1 < N) ? acc[mt][nt][3] + b1v : -3.4e38f;
            acc[mt][nt][0] = v0; acc[mt][nt][1] = v1;
            acc[mt][nt][2] = v2; acc[mt][nt][3] = v3;
            vmax[mt][0] = fmaxf(vmax[mt][0], fmaxf(v0, v1));
            vmax[mt][1] = fmaxf(vmax[mt][1], fmaxf(v2, v3));
        }
#pragma unroll
    for (int mt = 0; mt < 2; mt++)
#pragma unroll
        for (int hh = 0; hh < 2; hh++) {
            vmax[mt][hh] = fmaxf(vmax[mt][hh], __shfl_xor_sync(0xffffffffu, vmax[mt][hh], 1));
            vmax[mt][hh] = fmaxf(vmax[mt][hh], __shfl_xor_sync(0xffffffffu, vmax[mt][hh], 2));
        }
#pragma unroll
    for (int mt = 0; mt < 2; mt++) {
        int rin = wm * 32 + mt * 16 + lrow;
        sMx[rin][wn]     = vmax[mt][0];
        sMx[rin + 8][wn] = vmax[mt][1];
    }
    __syncthreads();
    float rmax[2][2], rsum[2][2];
#pragma unroll
    for (int mt = 0; mt < 2; mt++) {
        int rin = wm * 32 + mt * 16 + lrow;
        rmax[mt][0] = fmaxf(sMx[rin][0],     sMx[rin][1]);
        rmax[mt][1] = fmaxf(sMx[rin + 8][0], sMx[rin + 8][1]);
        rsum[mt][0] = 0.f; rsum[mt][1] = 0.f;
    }
#pragma unroll
    for (int mt = 0; mt < 2; mt++)
#pragma unroll
        for (int nt = 0; nt < 8; nt++) {
            rsum[mt][0] += __expf(acc[mt][nt][0] - rmax[mt][0])
                         + __expf(acc[mt][nt][1] - rmax[mt][0]);
            rsum[mt][1] += __expf(acc[mt][nt][2] - rmax[mt][1])
                         + __expf(acc[mt][nt][3] - rmax[mt][1]);
        }
#pragma unroll
    for (int mt = 0; mt < 2; mt++)
#pragma unroll
        for (int hh = 0; hh < 2; hh++) {
            rsum[mt][hh] += __shfl_xor_sync(0xffffffffu, rsum[mt][hh], 1);
            rsum[mt][hh] += __shfl_xor_sync(0xffffffffu, rsum[mt][hh], 2);
        }
#pragma unroll
    for (int mt = 0; mt < 2; mt++) {
        int rin = wm * 32 + mt * 16 + lrow;
        sSm[rin][wn]     = rsum[mt][0];
        sSm[rin + 8][wn] = rsum[mt][1];
    }
    __syncthreads();
    if (wn == 0 && (lane & 3) == 0) {
#pragma unroll
        for (int mt = 0; mt < 2; mt++) {
            int rin = wm * 32 + mt * 16 + lrow;
            int gr0 = mBase + rin, gr1 = gr0 + 8;
            g_pmax[(size_t)gr0 * NTILES + blockIdx.x] = rmax[mt][0];
            g_psum[(size_t)gr0 * NTILES + blockIdx.x] = sSm[rin][0] + sSm[rin][1];
            g_pmax[(size_t)gr1 * NTILES + blockIdx.x] = rmax[mt][1];
            g_psum[(size_t)gr1 * NTILES + blockIdx.x] = sSm[rin + 8][0] + sSm[rin + 8][1];
        }
    }
#pragma unroll
    for (int mt = 0; mt < 2; mt++) {
        int rin = wm * 32 + mt * 16 + lrow;
        int gr0 = mBase + rin, gr1 = gr0 + 8;
        int lab0 = labels[gr0], lab1 = labels[gr1];
#pragma unroll
        for (int nt = 0; nt < 8; nt++) {
            int col = nBase + wn * 64 + nt * 8 + lk;
            if (col == lab0)     g_labv[gr0] = acc[mt][nt][0];
            if (col + 1 == lab0) g_labv[gr0] = acc[mt][nt][1];
            if (col == lab1)     g_labv[gr1] = acc[mt][nt][2];
            if (col + 1 == lab1) g_labv[gr1] = acc[mt][nt][3];
        }
    }
}

// ---------------- merge loss partials: one warp per row ----------------
__global__ void loss_merge(const int* __restrict__ labels)
{
    int row  = (blockIdx.x * blockDim.x + threadIdx.x) >> 5;
    int lane = threadIdx.x & 31;
    if (row >= Mc) return;
    const float* pm = g_pmax + (size_t)row * NTILES;
    const float* ps = g_psum + (size_t)row * NTILES;
    float M = -3.4e38f;
    for (int i = lane; i < NTILES; i += 32) M = fmaxf(M, pm[i]);
#pragma unroll
    for (int o = 16; o > 0; o >>= 1) M = fmaxf(M, __shfl_xor_sync(0xffffffffu, M, o));
    float S = 0.f;
    for (int i = lane; i < NTILES; i += 32) S += ps[i] * __expf(pm[i] - M);
#pragma unroll
    for (int o = 16; o > 0; o >>= 1) S += __shfl_xor_sync(0xffffffffu, S, o);
    if (lane == 0) {
        int lab = labels[row];
        if (lab >= 0) {
            g_nll[row]   = (M + __logf(S)) - g_labv[row];
            g_valid[row] = 1.0f;
        } else {
            g_nll[row]   = 0.0f;
            g_valid[row] = 0.0f;
        }
    }
}

// ======================= Tensor-core attention (bf16 in-place score/P buffer, 2 CTAs/SM) =======================
#define AT_SQ    0
#define AT_SKV   2560
#define AT_SP    19968
#define AT_SINV  53248
#define AT_SMEM  53504

__global__ __launch_bounds__(256, 2)
void attn3_kernel(const bf16* __restrict__ qkv, bf16* __restrict__ ctx)
{
    extern __shared__ __align__(16) char sm[];
    uint16_t* sQ  = (uint16_t*)(sm + AT_SQ);
    uint16_t* sK  = (uint16_t*)(sm + AT_SKV);
    uint16_t* sVT = (uint16_t*)(sm + AT_SKV);
    bf16*     sSP = (bf16*)    (sm + AT_SP);
    float*    sInv= (float*)   (sm + AT_SINV);
    const uint32_t smb = smem_to_u32(sm);
    const uint32_t sQa = smb + AT_SQ;
    const uint32_t sKa = smb + AT_SKV;
    const uint32_t sVa = smb + AT_SKV;
    const uint32_t sPa = smb + AT_SP;

    const int t = threadIdx.x, lane = t & 31, w = t >> 5;
    const int q0 = blockIdx.x * 32;
    const int h  = blockIdx.y;
    const int b  = blockIdx.z;
    const int sp = g_sep[b];
    const int lrow = lane >> 2;
    const int lk   = 2 * (lane & 3);
    const int lane8 = lane & 7;
    const int Lmax = max(q0 + 31, sp);
    const int nch  = (Lmax >> 7) + 1;

    const bf16* qbase = qkv + (size_t)(b * Sc + q0) * QKVN + h * DHc;
    const bf16* kbase = qkv + (size_t)(b * Sc) * QKVN + Hc + h * DHc;
    const bf16* vbase = qkv + (size_t)(b * Sc) * QKVN + 2 * Hc + h * DHc;

    uint32_t aoffQ[2], aoffP[2];
#pragma unroll
    for (int mt = 0; mt < 2; mt++) {
        int arow = mt * 16 + ((lane >> 3) & 1) * 8 + lane8;
        int acol = (lane >> 4) * 8;
        aoffQ[mt] = (uint32_t)(arow * 40 + acol) * 2;
        aoffP[mt] = (uint32_t)(arow * 520 + acol) * 2;
    }
    const uint32_t boffK = (uint32_t)((w * 16 + ((lane >> 4) & 1) * 8 + lane8) * 40
                                      + ((lane >> 3) & 1) * 8) * 2;
    const uint32_t boffV = (uint32_t)((w * 8 + lane8) * 136 + ((lane >> 3) & 1) * 8) * 2;

#pragma unroll
    for (int i = 0; i < 2; i++) {
        int idx = t + i * 256;
        int r = idx >> 4, cg = idx & 15;
        uint2 v = *reinterpret_cast<const uint2*>(qbase + (size_t)r * QKVN + cg * 4);
        *reinterpret_cast<uint2*>(sQ + r * 40 + cg * 4) = v;
    }
    __syncthreads();

    for (int c = 0; c < nch; c++) {
        const int kb0 = c * 128;
#pragma unroll
        for (int i = 0; i < 8; i++) {
            int idx = t + i * 256;
            int r = idx >> 4, cg = idx & 15;
            uint2 v = *reinterpret_cast<const uint2*>(kbase + (size_t)(kb0 + r) * QKVN + cg * 4);
            *reinterpret_cast<uint2*>(sK + r * 40 + cg * 4) = v;
        }
        __syncthreads();

        float sacc[2][2][4];
#pragma unroll
        for (int mt = 0; mt < 2; mt++)
#pragma unroll
            for (int nt = 0; nt < 2; nt++)
#pragma unroll
                for (int i = 0; i < 4; i++) sacc[mt][nt][i] = 0.f;

#pragma unroll
        for (int ks = 0; ks < 4; ks++) {
            uint32_t af[2][4];
            ldmx4(af[0], sQa + aoffQ[0] + ks * 32);
            ldmx4(af[1], sQa + aoffQ[1] + ks * 32);
            uint32_t bf[4];
            ldmx4(bf, sKa + boffK + ks * 32);
            mma_bf16(sacc[0][0], af[0], bf[0], bf[1]);
            mma_bf16(sacc[1][0], af[1], bf[0], bf[1]);
            mma_bf16(sacc[0][1], af[0], bf[2], bf[3]);
            mma_bf16(sacc[1][1], af[1], bf[2], bf[3]);
        }
#pragma unroll
        for (int mt = 0; mt < 2; mt++) {
            const int r = mt * 16 + lrow;
#pragma unroll
            for (int nt = 0; nt < 2; nt++) {
                const int kcol = kb0 + w * 16 + nt * 8 + lk;
                bf162 lo, hi;
                lo.x = __float2bfloat16_rn(sacc[mt][nt][0] * 0.125f);
                lo.y = __float2bfloat16_rn(sacc[mt][nt][1] * 0.125f);
                hi.x = __float2bfloat16_rn(sacc[mt][nt][2] * 0.125f);
                hi.y = __float2bfloat16_rn(sacc[mt][nt][3] * 0.125f);
                *reinterpret_cast<bf162*>(sSP + r * 520 + kcol) = lo;
                *reinterpret_cast<bf162*>(sSP + (r + 8) * 520 + kcol) = hi;
            }
        }
        __syncthreads();
    }

    {
        const int r = t >> 3, sub = t & 7;
        const int Lk = max(q0 + r, sp);
        const int jmax = nch * 128;
        float m = -3.4e38f;
        for (int j = sub; j <= Lk; j += 8) m = fmaxf(m, __bfloat162float(sSP[r * 520 + j]));
#pragma unroll
        for (int msk = 1; msk < 8; msk <<= 1)
            m = fmaxf(m, __shfl_xor_sync(0xffffffffu, m, msk));
        float sum = 0.f;
        for (int j = sub; j < jmax; j += 8) {
            if (j <= Lk) {
                float e = __expf(__bfloat162float(sSP[r * 520 + j]) - m);
                sSP[r * 520 + j] = __float2bfloat16_rn(e);
                sum += e;
            } else {
                sSP[r * 520 + j] = __float2bfloat16_rn(0.f);
            }
        }
#pragma unroll
        for (int msk = 1; msk < 8; msk <<= 1)
            sum += __shfl_xor_sync(0xffffffffu, sum, msk);
        if (sub == 0) sInv[r] = 1.0f / sum;
    }
    __syncthreads();

    float cacc[2][4];
#pragma unroll
    for (int mt = 0; mt < 2; mt++)
#pragma unroll
        for (int i = 0; i < 4; i++) cacc[mt][i] = 0.f;

    for (int c = 0; c < nch; c++) {
        const int kb0 = c * 128;
#pragma unroll
        for (int i = 0; i < 8; i++) {
            int idx = t + i * 256;
            int kpos = idx >> 4, dg = idx & 15;
            uint2 v = *reinterpret_cast<const uint2*>(vbase + (size_t)(kb0 + kpos) * QKVN + dg * 4);
            sVT[(dg * 4 + 0) * 136 + kpos] = (uint16_t)(v.x);
            sVT[(dg * 4 + 1) * 136 + kpos] = (uint16_t)(v.x >> 16);
            sVT[(dg * 4 + 2) * 136 + kpos] = (uint16_t)(v.y);
            sVT[(dg * 4 + 3) * 136 + kpos] = (uint16_t)(v.y >> 16);
        }
        __syncthreads();
#pragma unroll
        for (int ks = 0; ks < 8; ks++) {
            uint32_t af[2][4];
            ldmx4(af[0], sPa + aoffP[0] + (kb0 + ks * 16) * 2);
            ldmx4(af[1], sPa + aoffP[1] + (kb0 + ks * 16) * 2);
            uint32_t bv[2];
            ldmx2(bv, sVa + boffV + ks * 32);
            mma_bf16(cacc[0], af[0], bv[0], bv[1]);
            mma_bf16(cacc[1], af[1], bv[0], bv[1]);
        }
        __syncthreads();
    }
#pragma unroll
    for (int mt = 0; mt < 2; mt++) {
        const int r = mt * 16 + lrow;
        const float inv0 = sInv[r], inv1 = sInv[r + 8];
        const int d0 = w * 8 + lk;
        bf162 lo, hi;
        lo.x = __float2bfloat16_rn(cacc[mt][0] * inv0);
        lo.y = __float2bfloat16_rn(cacc[mt][1] * inv0);
        hi.x = __float2bfloat16_rn(cacc[mt][2] * inv1);
        hi.y = __float2bfloat16_rn(cacc[mt][3] * inv1);
        *reinterpret_cast<bf162*>(ctx + (size_t)(b * Sc + q0 + r)     * Hc + h * DHc + d0) = lo;
        *reinterpret_cast<bf162*>(ctx + (size_t)(b * Sc + q0 + r + 8) * Hc + h * DHc + d0) = hi;
    }
}

// ---------------- Deterministic final reduction ----------------
__global__ void loss_reduce_kernel(float* __restrict__ out)
{
    __shared__ float rs[1024];
    __shared__ float rc[1024];
    int tid = threadIdx.x;
    float s = 0.f, c = 0.f;
    for (int i = tid; i < Mc; i += 1024) { s += g_nll[i]; c += g_valid[i]; }
    rs[tid] = s; rc[tid] = c; __syncthreads();
    for (int o = 512; o > 0; o >>= 1) {
        if (tid < o) { rs[tid] += rs[tid+o]; rc[tid] += rc[tid+o]; }
        __syncthreads();
    }
    if (tid == 0) out[0] = rs[0] / fmaxf(rc[0], 1.0f);
}

// ---------------- Host orchestration ----------------
static void run_tr_b(const float* in, bf16* out, int K, int N,
                     size_t inStride, size_t outStride, int layers)
{
    dim3 g((N + 31) / 32, (K + 63) / 64, layers);
    transpose_bf16_b<<<g, dim3(32, 8)>>>(in, out, K, N, inStride, outStride);
}

template<int ACT, int OUTBF>
static void run_gemm_t(const bf16* A, const bf16* Bt, const float* bias, void* C,
                       int M, int N, int K)
{
    dim3 grid((N + 127) / 128, M / 128);
    tc_gemm<ACT, OUTBF><<<grid, 256, GEMM_SMEM_BYTES>>>(A, Bt, bias, C, M, N, K);
}

template<int ACT, int OUTBF>
static void run_gemm64_t(const bf16* A, const bf16* Bt, const float* bias, void* C,
                         int M, int N, int K)
{
    dim3 grid((N + 127) / 128, M / 64);
    tc_gemm64<ACT, OUTBF><<<grid, 256, GEMM64_SMEM>>>(A, Bt, bias, C, M, N, K);
}

extern "C" void kernel_launch(void* const* d_in, const int* in_sizes, int n_in,
                              void* d_out, int out_size)
{
    (void)in_sizes; (void)n_in; (void)out_size;

    const int*   ids      = (const int*)  d_in[0];
    const int*   labels   = (const int*)  d_in[1];
    const float* word_emb = (const float*)d_in[2];
    const float* pos_emb  = (const float*)d_in[3];
    const float* type_emb = (const float*)d_in[4];
    const float* eg       = (const float*)d_in[5];
    const float* eb       = (const float*)d_in[6];
    const float* Wq       = (const float*)d_in[7];
    const float* bq       = (const float*)d_in[8];
    const float* Wk       = (const float*)d_in[9];
    const float* bk       = (const float*)d_in[10];
    const float* Wv       = (const float*)d_in[11];
    const float* bv       = (const float*)d_in[12];
    const float* Wo       = (const float*)d_in[13];
    const float* bo       = (const float*)d_in[14];
    const float* l1g      = (const float*)d_in[15];
    const float* l1b      = (const float*)d_in[16];
    const float* Wi       = (const float*)d_in[17];
    const float* bi       = (const float*)d_in[18];
    const float* Wd       = (const float*)d_in[19];
    const float* bd       = (const float*)d_in[20];
    const float* l2g      = (const float*)d_in[21];
    const float* l2b      = (const float*)d_in[22];
    const float* Wc       = (const float*)d_in[23];
    const float* bc       = (const float*)d_in[24];

    // SMEM opt-ins for every kernel above the 48KB default
    cudaFuncSetAttribute(attn3_kernel,  cudaFuncAttributeMaxDynamicSharedMemorySize, AT_SMEM);
    cudaFuncSetAttribute(tc_gemm<0,0>,  cudaFuncAttributeMaxDynamicSharedMemorySize, GEMM_SMEM_BYTES);
    cudaFuncSetAttribute(tc_gemm<0,1>,  cudaFuncAttributeMaxDynamicSharedMemorySize, GEMM_SMEM_BYTES);
    cudaFuncSetAttribute(tc_gemm<1,1>,  cudaFuncAttributeMaxDynamicSharedMemorySize, GEMM_SMEM_BYTES);
    cudaFuncSetAttribute(tc_gemm_loss,  cudaFuncAttributeMaxDynamicSharedMemorySize, GEMM_SMEM_BYTES);

    void* p;
    cudaGetSymbolAddress(&p, g_x);      float* px    = (float*)p;
    cudaGetSymbolAddress(&p, g_xb);     bf16*  pxb   = (bf16*)p;
    cudaGetSymbolAddress(&p, g_qkvb);   bf16*  pqkvb = (bf16*)p;
    cudaGetSymbolAddress(&p, g_ctxb);   bf16*  pctxb = (bf16*)p;
    cudaGetSymbolAddress(&p, g_proj);   float* pproj = (float*)p;
    cudaGetSymbolAddress(&p, g_ffnb);   bf16*  pffnb = (bf16*)p;
    cudaGetSymbolAddress(&p, g_bqkv);   float* pbqkv = (float*)p;
    cudaGetSymbolAddress(&p, g_WqkvT);  bf16*  pWqkvT= (bf16*)p;
    cudaGetSymbolAddress(&p, g_WoT);    bf16*  pWoT  = (bf16*)p;
    cudaGetSymbolAddress(&p, g_WiT);    bf16*  pWiT  = (bf16*)p;
    cudaGetSymbolAddress(&p, g_WdT);    bf16*  pWdT  = (bf16*)p;
    cudaGetSymbolAddress(&p, g_WcT);    bf16*  pWcT  = (bf16*)p;

    // Batched weight transposes (7 launches)
    const size_t HH = (size_t)Hc * Hc;
    run_tr_b(Wq, pWqkvT,                    Hc, Hc, HH, (size_t)QKVN*Hc, Lc);
    run_tr_b(Wk, pWqkvT + HH,               Hc, Hc, HH, (size_t)QKVN*Hc, Lc);
    run_tr_b(Wv, pWqkvT + 2*HH,             Hc, Hc, HH, (size_t)QKVN*Hc, Lc);
    run_tr_b(Wo, pWoT,                      Hc, Hc, HH, HH, Lc);
    run_tr_b(Wi, pWiT,  Hc, FFc, (size_t)Hc*FFc, (size_t)FFc*Hc, Lc);
    run_tr_b(Wd, pWdT,  FFc, Hc, (size_t)FFc*Hc, (size_t)Hc*FFc, Lc);
    run_tr_b(Wc, pWcT,  Hc, Vc,  0, 0, 1);

    build_qkv_bias<<<(Lc*QKVN + 255)/256, 256>>>(bq, bk, bv);
    sep_kernel<<<1, 32>>>(ids);
    embed_ln_kernel<<<Mc, 256>>>(ids, word_emb, pos_emb, type_emb, eg, eb);

    for (int l = 0; l < Lc; l++) {
        run_gemm_t<0,1>(pxb, pWqkvT + (size_t)l*QKVN*Hc, pbqkv + (size_t)l*QKVN,
                        pqkvb, Mc, QKVN, Hc);
        attn3_kernel<<<dim3(Sc/32, NHc, Bc), 256, AT_SMEM>>>(pqkvb, pctxb);
        run_gemm64_t<0,0>(pctxb, pWoT + (size_t)l*HH, bo + (size_t)l*Hc, pproj, Mc, Hc, Hc);
        add_ln_kernel<<<Mc, 256>>>(px, pxb, pproj, l1g + (size_t)l*Hc, l1b + (size_t)l*Hc);
        run_gemm_t<1,1>(pxb, pWiT + (size_t)l*FFc*Hc, bi + (size_t)l*FFc, pffnb, Mc, FFc, Hc);
        run_gemm64_t<0,0>(pffnb, pWdT + (size_t)l*Hc*FFc, bd + (size_t)l*Hc, pproj, Mc, Hc, FFc);
        add_ln_kernel<<<Mc, 256>>>(px, pxb, pproj, l2g + (size_t)l*Hc, l2b + (size_t)l*Hc);
    }

    // classifier + fused loss
    {
        dim3 grid(NTILES, Mc / 128);
        tc_gemm_loss<<<grid, 256, GEMM_SMEM_BYTES>>>(pxb, pWcT, bc, labels, Mc, Vc, Hc);
    }
    loss_merge<<<(Mc * 32 + 255) / 256, 256>>>(labels);
    loss_reduce_kernel<<<1, 1024>>>((float*)d_out);
}

// round 17
// speedup vs baseline: 1.1198x; 1.0452x over previous
#include <cuda_runtime.h>
#include <cuda_bf16.h>
#include <math.h>
#include <stdint.h>

// Problem constants
#define Lc 12
#define Hc 768
#define NHc 12
#define DHc 64
#define FFc 3072
#define Vc 21128
#define Sc 512
#define Bc 8
#define Mc (Bc*Sc)          // 4096 tokens
#define SEPc 102
#define LN_EPS 1e-12f
#define QKVN 2304
#define NTILES 166          // ceil(Vc/128)

typedef __nv_bfloat16 bf16;
typedef __nv_bfloat162 bf162;

// ---------------- Device scratch (static; no runtime allocation) ----------------
__device__ float g_x[Mc*Hc];               // fp32 residual stream
__device__ bf16  g_xb[Mc*Hc];              // bf16 copy of x (GEMM A operand)
__device__ bf16  g_qkvb[(size_t)Mc*QKVN];  // fused QKV output (bf16)
__device__ bf16  g_ctxb[Mc*Hc];            // attention output (bf16, feeds Wo)
__device__ float g_proj[Mc*Hc];            // fp32 GEMM output before residual+LN
__device__ bf16  g_ffnb[(size_t)Mc*FFc];   // GELU output (bf16, feeds Wd)
__device__ float g_pmax[(size_t)Mc*NTILES];
__device__ float g_psum[(size_t)Mc*NTILES];
__device__ float g_labv[Mc];
__device__ float g_nll[Mc];
__device__ float g_valid[Mc];
__device__ int   g_sep[Bc];
__device__ float g_bqkv[Lc*QKVN];          // fused QKV bias
// Transposed (N-major, K-contiguous) bf16 weights
__device__ bf16 g_WqkvT[(size_t)Lc*QKVN*Hc];
__device__ bf16 g_WoT[Lc*Hc*Hc];
__device__ bf16 g_WiT[(size_t)Lc*FFc*Hc];
__device__ bf16 g_WdT[(size_t)Lc*Hc*FFc];
__device__ bf16 g_WcT[(size_t)Vc*Hc];

// ---------------- small PTX helpers (compute_103-safe) ----------------
__device__ __forceinline__ uint32_t smem_to_u32(const void* smem_ptr) {
    uint32_t addr;
    asm("{ .reg .u64 tmp; cvta.to.shared.u64 tmp, %1; cvt.u32.u64 %0, tmp; }"
        : "=r"(addr) : "l"(smem_ptr));
    return addr;
}
__device__ __forceinline__ void cp16(uint32_t dst, const void* src, bool pred) {
    uint32_t sz = pred ? 16u : 0u;
    asm volatile("cp.async.cg.shared.global [%0], [%1], 16, %2;"
                 :: "r"(dst), "l"(src), "r"(sz));
}
#define CP_COMMIT() asm volatile("cp.async.commit_group;" ::: "memory")
#define CP_WAIT0()  asm volatile("cp.async.wait_group 0;" ::: "memory")
#define CP_WAIT1()  asm volatile("cp.async.wait_group 1;" ::: "memory")

__device__ __forceinline__ void mma_bf16(float* c, const uint32_t* a,
                                         uint32_t b0, uint32_t b1) {
    asm volatile(
        "mma.sync.aligned.m16n8k16.row.col.f32.bf16.bf16.f32 "
        "{%0,%1,%2,%3}, {%4,%5,%6,%7}, {%8,%9}, {%0,%1,%2,%3};"
        : "+f"(c[0]), "+f"(c[1]), "+f"(c[2]), "+f"(c[3])
        : "r"(a[0]), "r"(a[1]), "r"(a[2]), "r"(a[3]), "r"(b0), "r"(b1));
}
__device__ __forceinline__ void ldmx4(uint32_t* r, uint32_t addr) {
    asm volatile("ldmatrix.sync.aligned.m8n8.x4.shared.b16 {%0,%1,%2,%3}, [%4];"
        : "=r"(r[0]), "=r"(r[1]), "=r"(r[2]), "=r"(r[3]) : "r"(addr));
}
__device__ __forceinline__ void ldmx2(uint32_t* r, uint32_t addr) {
    asm volatile("ldmatrix.sync.aligned.m8n8.x2.shared.b16 {%0,%1}, [%2];"
        : "=r"(r[0]), "=r"(r[1]) : "r"(addr));
}

__device__ __forceinline__ float gelu_exact(float v) {
    return 0.5f * v * (1.0f + erff(v * 0.70710678118654752f));
}

// ---------------- Batched weight transpose + bf16 conversion (bf162 stores) ----------------
__global__ void transpose_bf16_b(const float* __restrict__ in, bf16* __restrict__ out,
                                 int K, int N, size_t inStride, size_t outStride)
{
    __shared__ float tile[64][33];
    in  += (size_t)blockIdx.z * inStride;
    out += (size_t)blockIdx.z * outStride;
    int kb = blockIdx.y * 64, nb = blockIdx.x * 32;
    int tx = threadIdx.x, ty = threadIdx.y;
    for (int i = ty; i < 64; i += 8) {
        int kk = kb + i, nn = nb + tx;
        tile[i][tx] = (kk < K && nn < N) ? in[(size_t)kk * N + nn] : 0.0f;
    }
    __syncthreads();
    for (int i = ty; i < 32; i += 8) {
        int nn = nb + i;
        int kk = kb + 2 * tx;
        if (nn < N && kk < K) {
            bf162 o;
            o.x = __float2bfloat16_rn(tile[2*tx][i]);
            o.y = __float2bfloat16_rn(tile[2*tx + 1][i]);
            *reinterpret_cast<bf162*>(out + (size_t)nn * K + kk) = o;
        }
    }
}

// ---------------- fused QKV bias ----------------
__global__ void build_qkv_bias(const float* __restrict__ bq, const float* __restrict__ bk,
                               const float* __restrict__ bv)
{
    int i = blockIdx.x * 256 + threadIdx.x;
    if (i < Lc * QKVN) {
        int l = i / QKVN, c = i % QKVN;
        float v;
        if (c < Hc)            v = bq[l*Hc + c];
        else if (c < 2*Hc)     v = bk[l*Hc + c - Hc];
        else                   v = bv[l*Hc + c - 2*Hc];
        g_bqkv[i] = v;
    }
}

// ---------------- [SEP] position per batch row ----------------
__global__ void sep_kernel(const int* __restrict__ ids) {
    int b = threadIdx.x;
    if (b < Bc) {
        int s = Sc - 1;
        for (int i = 0; i < Sc; i++) {
            if (ids[b*Sc + i] == SEPc) { s = i; break; }
        }
        g_sep[b] = s;
    }
}

// ---------------- Embedding + LayerNorm (dual fp32 + bf16 output) ----------------
__global__ void embed_ln_kernel(const int* __restrict__ ids,
                                const float* __restrict__ we,
                                const float* __restrict__ pe,
                                const float* __restrict__ te,
                                const float* __restrict__ gg,
                                const float* __restrict__ bb)
{
    int row = blockIdx.x;
    int s   = row % Sc;
    int tid = threadIdx.x;
    __shared__ float buf[Hc];
    __shared__ float wsum[8], wsq[8];
    int id = ids[row];
    float lsum = 0.f, lsq = 0.f;
    for (int j = tid; j < Hc; j += 256) {
        float val = we[(size_t)id*Hc + j] + pe[s*Hc + j] + te[j];
        buf[j] = val;
        lsum += val; lsq += val * val;
    }
#pragma unroll
    for (int o = 16; o > 0; o >>= 1) {
        lsum += __shfl_xor_sync(0xffffffffu, lsum, o);
        lsq  += __shfl_xor_sync(0xffffffffu, lsq,  o);
    }
    if ((tid & 31) == 0) { wsum[tid >> 5] = lsum; wsq[tid >> 5] = lsq; }
    __syncthreads();
    float ts = 0.f, tq = 0.f;
#pragma unroll
    for (int i = 0; i < 8; i++) { ts += wsum[i]; tq += wsq[i]; }
    float mean = ts * (1.0f/Hc);
    float var  = fmaxf(tq * (1.0f/Hc) - mean * mean, 0.f);
    float inv  = rsqrtf(var + LN_EPS);
    for (int j = tid; j < Hc; j += 256) {
        float o = (buf[j]-mean)*inv*gg[j] + bb[j];
        g_x[(size_t)row*Hc + j]  = o;
        g_xb[(size_t)row*Hc + j] = __float2bfloat16_rn(o);
    }
}

// ---------------- Residual add + LayerNorm, dual output ----------------
__global__ void add_ln_kernel(float* __restrict__ x, bf16* __restrict__ xb,
                              const float* __restrict__ t,
                              const float* __restrict__ gg, const float* __restrict__ bb)
{
    int row = blockIdx.x;
    int tid = threadIdx.x;
    __shared__ float buf[Hc];
    __shared__ float wsum[8], wsq[8];
    float lsum = 0.f, lsq = 0.f;
    for (int j = tid; j < Hc; j += 256) {
        float val = x[(size_t)row*Hc + j] + t[(size_t)row*Hc + j];
        buf[j] = val;
        lsum += val; lsq += val * val;
    }
#pragma unroll
    for (int o = 16; o > 0; o >>= 1) {
        lsum += __shfl_xor_sync(0xffffffffu, lsum, o);
        lsq  += __shfl_xor_sync(0xffffffffu, lsq,  o);
    }
    if ((tid & 31) == 0) { wsum[tid >> 5] = lsum; wsq[tid >> 5] = lsq; }
    __syncthreads();
    float ts = 0.f, tq = 0.f;
#pragma unroll
    for (int i = 0; i < 8; i++) { ts += wsum[i]; tq += wsq[i]; }
    float mean = ts * (1.0f/Hc);
    float var  = fmaxf(tq * (1.0f/Hc) - mean * mean, 0.f);
    float inv  = rsqrtf(var + LN_EPS);
    for (int j = tid; j < Hc; j += 256) {
        float o = (buf[j]-mean)*inv*gg[j] + bb[j];
        x[(size_t)row*Hc + j]  = o;
        xb[(size_t)row*Hc + j] = __float2bfloat16_rn(o);
    }
}

// ======================= mma.sync bf16 GEMM (3-stage pipeline + ldmatrix, 2 CTAs/SM) =======================
#define STG_HW 5120            // halfwords per stage (128*40)
#define STG_B  10240           // bytes per stage
#define GEMM_SMEM_BYTES 61440  // 6 buffers (A0-2, B0-2)

template<int ACT, int OUTBF>
__global__ __launch_bounds__(256, 2)
void tc_gemm(const bf16* __restrict__ A, const bf16* __restrict__ Bt,
             const float* __restrict__ bias, void* __restrict__ Cv,
             int M, int N, int K)
{
    extern __shared__ __align__(16) char smraw[];
    const uint32_t sbase = smem_to_u32(smraw);

    const int t    = threadIdx.x;
    const int lane = t & 31;
    const int w    = t >> 5;
    const int wm   = w & 3;
    const int wn   = w >> 2;
    const int m0   = blockIdx.y * 128;
    const int n0   = blockIdx.x * 128;
    const int nk   = K >> 5;

    float acc[2][8][4];
#pragma unroll
    for (int mt = 0; mt < 2; mt++)
#pragma unroll
        for (int nt = 0; nt < 8; nt++)
#pragma unroll
            for (int i = 0; i < 4; i++) acc[mt][nt][i] = 0.f;

    auto load_stage = [&](int c) {
        const int s  = c % 3;
        const int k0 = c << 5;
        const uint32_t aB = sbase + (uint32_t)s * STG_B;
        const uint32_t bB = sbase + 3u * STG_B + (uint32_t)s * STG_B;
#pragma unroll
        for (int i = 0; i < 2; i++) {
            int idx = t + i * 256;
            int row = idx >> 2, q = idx & 3;
            cp16(aB + (uint32_t)(row * 80 + q * 16),
                 A + (size_t)(m0 + row) * K + k0 + q * 8, true);
            int nr = n0 + row;
            bool p = nr < N;
            int nrc = p ? nr : 0;
            cp16(bB + (uint32_t)(row * 80 + q * 16),
                 Bt + (size_t)nrc * K + k0 + q * 8, p);
        }
        CP_COMMIT();
    };

    const int lane8 = lane & 7;
    uint32_t aoffB[2], boffB[4];
#pragma unroll
    for (int mt = 0; mt < 2; mt++) {
        int arow = wm * 32 + mt * 16 + ((lane >> 3) & 1) * 8 + lane8;
        int acol = (lane >> 4) * 8;
        aoffB[mt] = (uint32_t)(arow * 40 + acol) * 2;
    }
#pragma unroll
    for (int jp = 0; jp < 4; jp++) {
        int brow = wn * 64 + jp * 16 + ((lane >> 4) & 1) * 8 + lane8;
        int bcol = ((lane >> 3) & 1) * 8;
        boffB[jp] = (uint32_t)(brow * 40 + bcol) * 2;
    }

    load_stage(0);
    if (nk > 1) load_stage(1);
    for (int c = 0; c < nk; c++) {
        if (c + 1 < nk) { CP_WAIT1(); } else { CP_WAIT0(); }
        __syncthreads();
        if (c + 2 < nk) load_stage(c + 2);

        const int s = c % 3;
        const uint32_t aStage = sbase + (uint32_t)s * STG_B;
        const uint32_t bStage = sbase + 3u * STG_B + (uint32_t)s * STG_B;
#pragma unroll
        for (int ks = 0; ks < 2; ks++) {
            uint32_t af[2][4];
            ldmx4(af[0], aStage + aoffB[0] + ks * 32);
            ldmx4(af[1], aStage + aoffB[1] + ks * 32);
#pragma unroll
            for (int jp = 0; jp < 4; jp++) {
                uint32_t bf[4];
                ldmx4(bf, bStage + boffB[jp] + ks * 32);
                mma_bf16(acc[0][2*jp],     af[0], bf[0], bf[1]);
                mma_bf16(acc[1][2*jp],     af[1], bf[0], bf[1]);
                mma_bf16(acc[0][2*jp + 1], af[0], bf[2], bf[3]);
                mma_bf16(acc[1][2*jp + 1], af[1], bf[2], bf[3]);
            }
        }
    }

    const int lrow = lane >> 2;
    const int lk   = 2 * (lane & 3);
    float* Cf = (float*)Cv;
    bf16*  Cb = (bf16*)Cv;
#pragma unroll
    for (int mt = 0; mt < 2; mt++) {
        int rlo = m0 + wm * 32 + mt * 16 + lrow;
        int rhi = rlo + 8;
#pragma unroll
        for (int nt = 0; nt < 8; nt++) {
            int col = n0 + wn * 64 + nt * 8 + lk;
            if (col < N) {
                float b0v = bias[col], b1v = bias[col + 1];
                float v0 = acc[mt][nt][0] + b0v;
                float v1 = acc[mt][nt][1] + b1v;
                float v2 = acc[mt][nt][2] + b0v;
                float v3 = acc[mt][nt][3] + b1v;
                if (ACT == 1) {
                    v0 = gelu_exact(v0); v1 = gelu_exact(v1);
                    v2 = gelu_exact(v2); v3 = gelu_exact(v3);
                }
                if (OUTBF) {
                    bf162 lo; lo.x = __float2bfloat16_rn(v0); lo.y = __float2bfloat16_rn(v1);
                    bf162 hi; hi.x = __float2bfloat16_rn(v2); hi.y = __float2bfloat16_rn(v3);
                    *reinterpret_cast<bf162*>(Cb + (size_t)rlo * N + col) = lo;
                    *reinterpret_cast<bf162*>(Cb + (size_t)rhi * N + col) = hi;
                } else {
                    float2 lo; lo.x = v0; lo.y = v1;
                    float2 hi; hi.x = v2; hi.y = v3;
                    *reinterpret_cast<float2*>(Cf + (size_t)rlo * N + col) = lo;
                    *reinterpret_cast<float2*>(Cf + (size_t)rhi * N + col) = hi;
                }
            }
        }
    }
}

// ======================= 64-row-M-tile GEMM (for N=768 GEMMs; better wave balance) =======================
#define STG64_A_B 5120         // 64*40 hw * 2B
#define GEMM64_SMEM (3*STG64_A_B + 3*STG_B)   // 46080

template<int ACT, int OUTBF>
__global__ __launch_bounds__(256, 3)
void tc_gemm64(const bf16* __restrict__ A, const bf16* __restrict__ Bt,
               const float* __restrict__ bias, void* __restrict__ Cv,
               int M, int N, int K)
{
    extern __shared__ __align__(16) char smraw[];
    const uint32_t sbase = smem_to_u32(smraw);

    const int t    = threadIdx.x;
    const int lane = t & 31;
    const int w    = t >> 5;
    const int wm   = w & 1;
    const int wn   = w >> 1;
    const int m0   = blockIdx.y * 64;
    const int n0   = blockIdx.x * 128;
    const int nk   = K >> 5;

    float acc[2][4][4];
#pragma unroll
    for (int mt = 0; mt < 2; mt++)
#pragma unroll
        for (int nt = 0; nt < 4; nt++)
#pragma unroll
            for (int i = 0; i < 4; i++) acc[mt][nt][i] = 0.f;

    auto load_stage = [&](int c) {
        const int s  = c % 3;
        const int k0 = c << 5;
        const uint32_t aB = sbase + (uint32_t)s * STG64_A_B;
        const uint32_t bB = sbase + 3u * STG64_A_B + (uint32_t)s * STG_B;
        {
            int row = t >> 2, q = t & 3;
            cp16(aB + (uint32_t)(row * 80 + q * 16),
                 A + (size_t)(m0 + row) * K + k0 + q * 8, true);
        }
#pragma unroll
        for (int i = 0; i < 2; i++) {
            int idx = t + i * 256;
            int row = idx >> 2, q = idx & 3;
            int nr = n0 + row;
            bool p = nr < N;
            int nrc = p ? nr : 0;
            cp16(bB + (uint32_t)(row * 80 + q * 16),
                 Bt + (size_t)nrc * K + k0 + q * 8, p);
        }
        CP_COMMIT();
    };

    const int lane8 = lane & 7;
    uint32_t aoffB[2], boffB[2];
#pragma unroll
    for (int mt = 0; mt < 2; mt++) {
        int arow = wm * 32 + mt * 16 + ((lane >> 3) & 1) * 8 + lane8;
        int acol = (lane >> 4) * 8;
        aoffB[mt] = (uint32_t)(arow * 40 + acol) * 2;
    }
#pragma unroll
    for (int jp = 0; jp < 2; jp++) {
        int brow = wn * 32 + jp * 16 + ((lane >> 4) & 1) * 8 + lane8;
        int bcol = ((lane >> 3) & 1) * 8;
        boffB[jp] = (uint32_t)(brow * 40 + bcol) * 2;
    }

    load_stage(0);
    if (nk > 1) load_stage(1);
    for (int c = 0; c < nk; c++) {
        if (c + 1 < nk) { CP_WAIT1(); } else { CP_WAIT0(); }
        __syncthreads();
        if (c + 2 < nk) load_stage(c + 2);

        const int s = c % 3;
        const uint32_t aStage = sbase + (uint32_t)s * STG64_A_B;
        const uint32_t bStage = sbase + 3u * STG64_A_B + (uint32_t)s * STG_B;
#pragma unroll
        for (int ks = 0; ks < 2; ks++) {
            uint32_t af[2][4];
            ldmx4(af[0], aStage + aoffB[0] + ks * 32);
            ldmx4(af[1], aStage + aoffB[1] + ks * 32);
#pragma unroll
            for (int jp = 0; jp < 2; jp++) {
                uint32_t bf[4];
                ldmx4(bf, bStage + boffB[jp] + ks * 32);
                mma_bf16(acc[0][2*jp],     af[0], bf[0], bf[1]);
                mma_bf16(acc[1][2*jp],     af[1], bf[0], bf[1]);
                mma_bf16(acc[0][2*jp + 1], af[0], bf[2], bf[3]);
                mma_bf16(acc[1][2*jp + 1], af[1], bf[2], bf[3]);
            }
        }
    }

    const int lrow = lane >> 2;
    const int lk   = 2 * (lane & 3);
    float* Cf = (float*)Cv;
    bf16*  Cb = (bf16*)Cv;
#pragma unroll
    for (int mt = 0; mt < 2; mt++) {
        int rlo = m0 + wm * 32 + mt * 16 + lrow;
        int rhi = rlo + 8;
#pragma unroll
        for (int nt = 0; nt < 4; nt++) {
            int col = n0 + wn * 32 + nt * 8 + lk;
            if (col < N) {
                float b0v = bias[col], b1v = bias[col + 1];
                float v0 = acc[mt][nt][0] + b0v;
                float v1 = acc[mt][nt][1] + b1v;
                float v2 = acc[mt][nt][2] + b0v;
                float v3 = acc[mt][nt][3] + b1v;
                if (ACT == 1) {
                    v0 = gelu_exact(v0); v1 = gelu_exact(v1);
                    v2 = gelu_exact(v2); v3 = gelu_exact(v3);
                }
                if (OUTBF) {
                    bf162 lo; lo.x = __float2bfloat16_rn(v0); lo.y = __float2bfloat16_rn(v1);
                    bf162 hi; hi.x = __float2bfloat16_rn(v2); hi.y = __float2bfloat16_rn(v3);
                    *reinterpret_cast<bf162*>(Cb + (size_t)rlo * N + col) = lo;
                    *reinterpret_cast<bf162*>(Cb + (size_t)rhi * N + col) = hi;
                } else {
                    float2 lo; lo.x = v0; lo.y = v1;
                    float2 hi; hi.x = v2; hi.y = v3;
                    *reinterpret_cast<float2*>(Cf + (size_t)rlo * N + col) = lo;
                    *reinterpret_cast<float2*>(Cf + (size_t)rhi * N + col) = hi;
                }
            }
        }
    }
}

// ======================= Classifier GEMM + fused log-softmax partials =======================
__global__ __launch_bounds__(256, 2)
void tc_gemm_loss(const bf16* __restrict__ A, const bf16* __restrict__ Bt,
                  const float* __restrict__ bias, const int* __restrict__ labels,
                  int M, int N, int K)
{
    extern __shared__ __align__(16) char smraw[];
    const uint32_t sbase = smem_to_u32(smraw);
    __shared__ float sMx[128][2];
    __shared__ float sSm[128][2];

    const int t    = threadIdx.x;
    const int lane = t & 31;
    const int w    = t >> 5;
    const int wm   = w & 3;
    const int wn   = w >> 2;
    const int mBase = blockIdx.y * 128;
    const int nBase = blockIdx.x * 128;
    const int nk   = K >> 5;

    float acc[2][8][4];
#pragma unroll
    for (int mt = 0; mt < 2; mt++)
#pragma unroll
        for (int nt = 0; nt < 8; nt++)
#pragma unroll
            for (int i = 0; i < 4; i++) acc[mt][nt][i] = 0.f;

    auto load_stage = [&](int c) {
        const int s  = c % 3;
        const int k0 = c << 5;
        const uint32_t aB = sbase + (uint32_t)s * STG_B;
        const uint32_t bB = sbase + 3u * STG_B + (uint32_t)s * STG_B;
#pragma unroll
        for (int i = 0; i < 2; i++) {
            int idx = t + i * 256;
            int row = idx >> 2, q = idx & 3;
            cp16(aB + (uint32_t)(row * 80 + q * 16),
                 A + (size_t)(mBase + row) * K + k0 + q * 8, true);
            int nr = nBase + row;
            bool p = nr < N;
            int nrc = p ? nr : 0;
            cp16(bB + (uint32_t)(row * 80 + q * 16),
                 Bt + (size_t)nrc * K + k0 + q * 8, p);
        }
        CP_COMMIT();
    };

    const int lane8 = lane & 7;
    uint32_t aoffB[2], boffB[4];
#pragma unroll
    for (int mt = 0; mt < 2; mt++) {
        int arow = wm * 32 + mt * 16 + ((lane >> 3) & 1) * 8 + lane8;
        int acol = (lane >> 4) * 8;
        aoffB[mt] = (uint32_t)(arow * 40 + acol) * 2;
    }
#pragma unroll
    for (int jp = 0; jp < 4; jp++) {
        int brow = wn * 64 + jp * 16 + ((lane >> 4) & 1) * 8 + lane8;
        int bcol = ((lane >> 3) & 1) * 8;
        boffB[jp] = (uint32_t)(brow * 40 + bcol) * 2;
    }

    const int lrow = lane >> 2;
    const int lk   = 2 * (lane & 3);

    load_stage(0);
    if (nk > 1) load_stage(1);
    for (int c = 0; c < nk; c++) {
        if (c + 1 < nk) { CP_WAIT1(); } else { CP_WAIT0(); }
        __syncthreads();
        if (c + 2 < nk) load_stage(c + 2);

        const int s = c % 3;
        const uint32_t aStage = sbase + (uint32_t)s * STG_B;
        const uint32_t bStage = sbase + 3u * STG_B + (uint32_t)s * STG_B;
#pragma unroll
        for (int ks = 0; ks < 2; ks++) {
            uint32_t af[2][4];
            ldmx4(af[0], aStage + aoffB[0] + ks * 32);
            ldmx4(af[1], aStage + aoffB[1] + ks * 32);
#pragma unroll
            for (int jp = 0; jp < 4; jp++) {
                uint32_t bf[4];
                ldmx4(bf, bStage + boffB[jp] + ks * 32);
                mma_bf16(acc[0][2*jp],     af[0], bf[0], bf[1]);
                mma_bf16(acc[1][2*jp],     af[1], bf[0], bf[1]);
                mma_bf16(acc[0][2*jp + 1], af[0], bf[2], bf[3]);
                mma_bf16(acc[1][2*jp + 1], af[1], bf[2], bf[3]);
            }
        }
    }
    __syncthreads();

    // ---- loss epilogue ----
    float vmax[2][2];
#pragma unroll
    for (int mt = 0; mt < 2; mt++) { vmax[mt][0] = -3.4e38f; vmax[mt][1] = -3.4e38f; }
#pragma unroll
    for (int mt = 0; mt < 2; mt++)
#pragma unroll
        for (int nt = 0; nt < 8; nt++) {
            int col = nBase + wn * 64 + nt * 8 + lk;
            float b0v = (col     < N) ? bias[col]     : 0.f;
            float b1v = (col + 1 < N) ? bias[col + 1] : 0.f;
            float v0 = (col     < N) ? acc[mt][nt][0] + b0v : -3.4e38f;
            float v1 = (col + 1 < N) ? acc[mt][nt][1] + b1v : -3.4e38f;
            float v2 = (col     < N) ? acc[mt][nt][2] + b0v : -3.4e38f;
            float v3 = (col + 1 < N) ? acc[mt][nt][3] + b1v : -3.4e38f;
            acc[mt][nt][0] = v0; acc[mt][nt][1] = v1;
            acc[mt][nt][2] = v2; acc[mt][nt][3] = v3;
            vmax[mt][0] = fmaxf(vmax[mt][0], fmaxf(v0, v1));
            vmax[mt][1] = fmaxf(vmax[mt][1], fmaxf(v2, v3));
        }
#pragma unroll
    for (int mt = 0; mt < 2; mt++)
#pragma unroll
        for (int hh = 0; hh < 2; hh++) {
            vmax[mt][hh] = fmaxf(vmax[mt][hh], __shfl_xor_sync(0xffffffffu, vmax[mt][hh], 1));
            vmax[mt][hh] = fmaxf(vmax[mt][hh], __shfl_xor_sync(0xffffffffu, vmax[mt][hh], 2));
        }
#pragma unroll
    for (int mt = 0; mt < 2; mt++) {
        int rin = wm * 32 + mt * 16 + lrow;
        sMx[rin][wn]     = vmax[mt][0];
        sMx[rin + 8][wn] = vmax[mt][1];
    }
    __syncthreads();
    float rmax[2][2], rsum[2][2];
#pragma unroll
    for (int mt = 0; mt < 2; mt++) {
        int rin = wm * 32 + mt * 16 + lrow;
        rmax[mt][0] = fmaxf(sMx[rin][0],     sMx[rin][1]);
        rmax[mt][1] = fmaxf(sMx[rin + 8][0], sMx[rin + 8][1]);
        rsum[mt][0] = 0.f; rsum[mt][1] = 0.f;
    }
#pragma unroll
    for (int mt = 0; mt < 2; mt++)
#pragma unroll
        for (int nt = 0; nt < 8; nt++) {
            rsum[mt][0] += __expf(acc[mt][nt][0] - rmax[mt][0])
                         + __expf(acc[mt][nt][1] - rmax[mt][0]);
            rsum[mt][1] += __expf(acc[mt][nt][2] - rmax[mt][1])
                         + __expf(acc[mt][nt][3] - rmax[mt][1]);
        }
#pragma unroll
    for (int mt = 0; mt < 2; mt++)
#pragma unroll
        for (int hh = 0; hh < 2; hh++) {
            rsum[mt][hh] += __shfl_xor_sync(0xffffffffu, rsum[mt][hh], 1);
            rsum[mt][hh] += __shfl_xor_sync(0xffffffffu, rsum[mt][hh], 2);
        }
#pragma unroll
    for (int mt = 0; mt < 2; mt++) {
        int rin = wm * 32 + mt * 16 + lrow;
        sSm[rin][wn]     = rsum[mt][0];
        sSm[rin + 8][wn] = rsum[mt][1];
    }
    __syncthreads();
    if (wn == 0 && (lane & 3) == 0) {
#pragma unroll
        for (int mt = 0; mt < 2; mt++) {
            int rin = wm * 32 + mt * 16 + lrow;
            int gr0 = mBase + rin, gr1 = gr0 + 8;
            g_pmax[(size_t)gr0 * NTILES + blockIdx.x] = rmax[mt][0];
            g_psum[(size_t)gr0 * NTILES + blockIdx.x] = sSm[rin][0] + sSm[rin][1];
            g_pmax[(size_t)gr1 * NTILES + blockIdx.x] = rmax[mt][1];
            g_psum[(size_t)gr1 * NTILES + blockIdx.x] = sSm[rin + 8][0] + sSm[rin + 8][1];
        }
    }
#pragma unroll
    for (int mt = 0; mt < 2; mt++) {
        int rin = wm * 32 + mt * 16 + lrow;
        int gr0 = mBase + rin, gr1 = gr0 + 8;
        int lab0 = labels[gr0], lab1 = labels[gr1];
#pragma unroll
        for (int nt = 0; nt < 8; nt++) {
            int col = nBase + wn * 64 + nt * 8 + lk;
            if (col == lab0)     g_labv[gr0] = acc[mt][nt][0];
            if (col + 1 == lab0) g_labv[gr0] = acc[mt][nt][1];
            if (col == lab1)     g_labv[gr1] = acc[mt][nt][2];
            if (col + 1 == lab1) g_labv[gr1] = acc[mt][nt][3];
        }
    }
}

// ---------------- merge loss partials: one warp per row ----------------
__global__ void loss_merge(const int* __restrict__ labels)
{
    int row  = (blockIdx.x * blockDim.x + threadIdx.x) >> 5;
    int lane = threadIdx.x & 31;
    if (row >= Mc) return;
    const float* pm = g_pmax + (size_t)row * NTILES;
    const float* ps = g_psum + (size_t)row * NTILES;
    float M = -3.4e38f;
    for (int i = lane; i < NTILES; i += 32) M = fmaxf(M, pm[i]);
#pragma unroll
    for (int o = 16; o > 0; o >>= 1) M = fmaxf(M, __shfl_xor_sync(0xffffffffu, M, o));
    float S = 0.f;
    for (int i = lane; i < NTILES; i += 32) S += ps[i] * __expf(pm[i] - M);
#pragma unroll
    for (int o = 16; o > 0; o >>= 1) S += __shfl_xor_sync(0xffffffffu, S, o);
    if (lane == 0) {
        int lab = labels[row];
        if (lab >= 0) {
            g_nll[row]   = (M + __logf(S)) - g_labv[row];
            g_valid[row] = 1.0f;
        } else {
            g_nll[row]   = 0.0f;
            g_valid[row] = 0.0f;
        }
    }
}

// ======================= Tensor-core attention (64-q tile, bf16 in-place P, 2 CTAs/SM) =======================
// SMEM: sQ[64][40] bf16 @0 (5120B) | sK[128][40]/sVT[64][136] union @5120 (17408B)
//       | sSP[64][520] bf16 @22528 (66560B) | sInv[64] @89088 ; total 89344
#define AT_SQ    0
#define AT_SKV   5120
#define AT_SP    22528
#define AT_SINV  89088
#define AT_SMEM  89344

__global__ __launch_bounds__(256, 2)
void attn3_kernel(const bf16* __restrict__ qkv, bf16* __restrict__ ctx)
{
    extern __shared__ __align__(16) char sm[];
    uint16_t* sQ  = (uint16_t*)(sm + AT_SQ);
    uint16_t* sK  = (uint16_t*)(sm + AT_SKV);
    uint16_t* sVT = (uint16_t*)(sm + AT_SKV);
    bf16*     sSP = (bf16*)    (sm + AT_SP);
    float*    sInv= (float*)   (sm + AT_SINV);
    const uint32_t smb = smem_to_u32(sm);
    const uint32_t sQa = smb + AT_SQ;
    const uint32_t sKa = smb + AT_SKV;
    const uint32_t sVa = smb + AT_SKV;
    const uint32_t sPa = smb + AT_SP;

    const int t = threadIdx.x, lane = t & 31, w = t >> 5;
    const int q0 = blockIdx.x * 64;
    const int h  = blockIdx.y;
    const int b  = blockIdx.z;
    const int sp = g_sep[b];
    const int lrow = lane >> 2;
    const int lk   = 2 * (lane & 3);
    const int lane8 = lane & 7;
    const int Lmax = max(q0 + 63, sp);
    const int nch  = (Lmax >> 7) + 1;

    const bf16* qbase = qkv + (size_t)(b * Sc + q0) * QKVN + h * DHc;
    const bf16* kbase = qkv + (size_t)(b * Sc) * QKVN + Hc + h * DHc;
    const bf16* vbase = qkv + (size_t)(b * Sc) * QKVN + 2 * Hc + h * DHc;

    uint32_t aoffQ[4], aoffP[4];
#pragma unroll
    for (int mt = 0; mt < 4; mt++) {
        int arow = mt * 16 + ((lane >> 3) & 1) * 8 + lane8;
        int acol = (lane >> 4) * 8;
        aoffQ[mt] = (uint32_t)(arow * 40 + acol) * 2;
        aoffP[mt] = (uint32_t)(arow * 520 + acol) * 2;
    }
    const uint32_t boffK = (uint32_t)((w * 16 + ((lane >> 4) & 1) * 8 + lane8) * 40
                                      + ((lane >> 3) & 1) * 8) * 2;
    const uint32_t boffV = (uint32_t)((w * 8 + lane8) * 136 + ((lane >> 3) & 1) * 8) * 2;

    // ---- load Q tile (64 x 64): 1024 chunks of 4 hw ----
#pragma unroll
    for (int i = 0; i < 4; i++) {
        int idx = t + i * 256;
        int r = idx >> 4, cg = idx & 15;
        uint2 v = *reinterpret_cast<const uint2*>(qbase + (size_t)r * QKVN + cg * 4);
        *reinterpret_cast<uint2*>(sQ + r * 40 + cg * 4) = v;
    }
    __syncthreads();

    // ---- QK^T scores ----
    for (int c = 0; c < nch; c++) {
        const int kb0 = c * 128;
#pragma unroll
        for (int i = 0; i < 8; i++) {
            int idx = t + i * 256;
            int r = idx >> 4, cg = idx & 15;
            uint2 v = *reinterpret_cast<const uint2*>(kbase + (size_t)(kb0 + r) * QKVN + cg * 4);
            *reinterpret_cast<uint2*>(sK + r * 40 + cg * 4) = v;
        }
        __syncthreads();

        float sacc[4][2][4];
#pragma unroll
        for (int mt = 0; mt < 4; mt++)
#pragma unroll
            for (int nt = 0; nt < 2; nt++)
#pragma unroll
                for (int i = 0; i < 4; i++) sacc[mt][nt][i] = 0.f;

#pragma unroll
        for (int ks = 0; ks < 4; ks++) {
            uint32_t bf[4];
            ldmx4(bf, sKa + boffK + ks * 32);
#pragma unroll
            for (int mt = 0; mt < 4; mt++) {
                uint32_t af[4];
                ldmx4(af, sQa + aoffQ[mt] + ks * 32);
                mma_bf16(sacc[mt][0], af, bf[0], bf[1]);
                mma_bf16(sacc[mt][1], af, bf[2], bf[3]);
            }
        }
#pragma unroll
        for (int mt = 0; mt < 4; mt++) {
            const int r = mt * 16 + lrow;
#pragma unroll
            for (int nt = 0; nt < 2; nt++) {
                const int kcol = kb0 + w * 16 + nt * 8 + lk;
                bf162 lo, hi;
                lo.x = __float2bfloat16_rn(sacc[mt][nt][0] * 0.125f);
                lo.y = __float2bfloat16_rn(sacc[mt][nt][1] * 0.125f);
                hi.x = __float2bfloat16_rn(sacc[mt][nt][2] * 0.125f);
                hi.y = __float2bfloat16_rn(sacc[mt][nt][3] * 0.125f);
                *reinterpret_cast<bf162*>(sSP + r * 520 + kcol) = lo;
                *reinterpret_cast<bf162*>(sSP + (r + 8) * 520 + kcol) = hi;
            }
        }
        __syncthreads();
    }

    // ---- softmax: 4 threads per row over 64 rows; in-place exp; zero-fill rest ----
    {
        const int r = t >> 2, sub = t & 3;
        const int Lk = max(q0 + r, sp);
        const int jmax = nch * 128;
        float m = -3.4e38f;
        for (int j = sub; j <= Lk; j += 4) m = fmaxf(m, __bfloat162float(sSP[r * 520 + j]));
#pragma unroll
        for (int msk = 1; msk < 4; msk <<= 1)
            m = fmaxf(m, __shfl_xor_sync(0xffffffffu, m, msk));
        float sum = 0.f;
        for (int j = sub; j < jmax; j += 4) {
            if (j <= Lk) {
                float e = __expf(__bfloat162float(sSP[r * 520 + j]) - m);
                sSP[r * 520 + j] = __float2bfloat16_rn(e);
                sum += e;
            } else {
                sSP[r * 520 + j] = __float2bfloat16_rn(0.f);
            }
        }
#pragma unroll
        for (int msk = 1; msk < 4; msk <<= 1)
            sum += __shfl_xor_sync(0xffffffffu, sum, msk);
        if (sub == 0) sInv[r] = 1.0f / sum;
    }
    __syncthreads();

    // ---- ctx = P @ V (warp w owns d cols w*8..w*8+7, all 64 q rows) ----
    float cacc[4][4];
#pragma unroll
    for (int mt = 0; mt < 4; mt++)
#pragma unroll
        for (int i = 0; i < 4; i++) cacc[mt][i] = 0.f;

    for (int c = 0; c < nch; c++) {
        const int kb0 = c * 128;
#pragma unroll
        for (int i = 0; i < 8; i++) {
            int idx = t + i * 256;
            int kpos = idx >> 4, dg = idx & 15;
            uint2 v = *reinterpret_cast<const uint2*>(vbase + (size_t)(kb0 + kpos) * QKVN + dg * 4);
            sVT[(dg * 4 + 0) * 136 + kpos] = (uint16_t)(v.x);
            sVT[(dg * 4 + 1) * 136 + kpos] = (uint16_t)(v.x >> 16);
            sVT[(dg * 4 + 2) * 136 + kpos] = (uint16_t)(v.y);
            sVT[(dg * 4 + 3) * 136 + kpos] = (uint16_t)(v.y >> 16);
        }
        __syncthreads();
#pragma unroll
        for (int ks = 0; ks < 8; ks++) {
            uint32_t bv[2];
            ldmx2(bv, sVa + boffV + ks * 32);
#pragma unroll
            for (int mt = 0; mt < 4; mt++) {
                uint32_t af[4];
                ldmx4(af, sPa + aoffP[mt] + (kb0 + ks * 16) * 2);
                mma_bf16(cacc[mt], af, bv[0], bv[1]);
            }
        }
        __syncthreads();
    }
#pragma unroll
    for (int mt = 0; mt < 4; mt++) {
        const int r = mt * 16 + lrow;
        const float inv0 = sInv[r], inv1 = sInv[r + 8];
        const int d0 = w * 8 + lk;
        bf162 lo, hi;
        lo.x = __float2bfloat16_rn(cacc[mt][0] * inv0);
        lo.y = __float2bfloat16_rn(cacc[mt][1] * inv0);
        hi.x = __float2bfloat16_rn(cacc[mt][2] * inv1);
        hi.y = __float2bfloat16_rn(cacc[mt][3] * inv1);
        *reinterpret_cast<bf162*>(ctx + (size_t)(b * Sc + q0 + r)     * Hc + h * DHc + d0) = lo;
        *reinterpret_cast<bf162*>(ctx + (size_t)(b * Sc + q0 + r + 8) * Hc + h * DHc + d0) = hi;
    }
}

// ---------------- Deterministic final reduction ----------------
__global__ void loss_reduce_kernel(float* __restrict__ out)
{
    __shared__ float rs[1024];
    __shared__ float rc[1024];
    int tid = threadIdx.x;
    float s = 0.f, c = 0.f;
    for (int i = tid; i < Mc; i += 1024) { s += g_nll[i]; c += g_valid[i]; }
    rs[tid] = s; rc[tid] = c; __syncthreads();
    for (int o = 512; o > 0; o >>= 1) {
        if (tid < o) { rs[tid] += rs[tid+o]; rc[tid] += rc[tid+o]; }
        __syncthreads();
    }
    if (tid == 0) out[0] = rs[0] / fmaxf(rc[0], 1.0f);
}

// ---------------- Host orchestration ----------------
static void run_tr_b(const float* in, bf16* out, int K, int N,
                     size_t inStride, size_t outStride, int layers)
{
    dim3 g((N + 31) / 32, (K + 63) / 64, layers);
    transpose_bf16_b<<<g, dim3(32, 8)>>>(in, out, K, N, inStride, outStride);
}

template<int ACT, int OUTBF>
static void run_gemm_t(const bf16* A, const bf16* Bt, const float* bias, void* C,
                       int M, int N, int K)
{
    dim3 grid((N + 127) / 128, M / 128);
    tc_gemm<ACT, OUTBF><<<grid, 256, GEMM_SMEM_BYTES>>>(A, Bt, bias, C, M, N, K);
}

template<int ACT, int OUTBF>
static void run_gemm64_t(const bf16* A, const bf16* Bt, const float* bias, void* C,
                         int M, int N, int K)
{
    dim3 grid((N + 127) / 128, M / 64);
    tc_gemm64<ACT, OUTBF><<<grid, 256, GEMM64_SMEM>>>(A, Bt, bias, C, M, N, K);
}

extern "C" void kernel_launch(void* const* d_in, const int* in_sizes, int n_in,
                              void* d_out, int out_size)
{
    (void)in_sizes; (void)n_in; (void)out_size;

    const int*   ids      = (const int*)  d_in[0];
    const int*   labels   = (const int*)  d_in[1];
    const float* word_emb = (const float*)d_in[2];
    const float* pos_emb  = (const float*)d_in[3];
    const float* type_emb = (const float*)d_in[4];
    const float* eg       = (const float*)d_in[5];
    const float* eb       = (const float*)d_in[6];
    const float* Wq       = (const float*)d_in[7];
    const float* bq       = (const float*)d_in[8];
    const float* Wk       = (const float*)d_in[9];
    const float* bk       = (const float*)d_in[10];
    const float* Wv       = (const float*)d_in[11];
    const float* bv       = (const float*)d_in[12];
    const float* Wo       = (const float*)d_in[13];
    const float* bo       = (const float*)d_in[14];
    const float* l1g      = (const float*)d_in[15];
    const float* l1b      = (const float*)d_in[16];
    const float* Wi       = (const float*)d_in[17];
    const float* bi       = (const float*)d_in[18];
    const float* Wd       = (const float*)d_in[19];
    const float* bd       = (const float*)d_in[20];
    const float* l2g      = (const float*)d_in[21];
    const float* l2b      = (const float*)d_in[22];
    const float* Wc       = (const float*)d_in[23];
    const float* bc       = (const float*)d_in[24];

    // SMEM opt-ins for every kernel above the 48KB default
    cudaFuncSetAttribute(attn3_kernel,  cudaFuncAttributeMaxDynamicSharedMemorySize, AT_SMEM);
    cudaFuncSetAttribute(tc_gemm<0,0>,  cudaFuncAttributeMaxDynamicSharedMemorySize, GEMM_SMEM_BYTES);
    cudaFuncSetAttribute(tc_gemm<0,1>,  cudaFuncAttributeMaxDynamicSharedMemorySize, GEMM_SMEM_BYTES);
    cudaFuncSetAttribute(tc_gemm<1,1>,  cudaFuncAttributeMaxDynamicSharedMemorySize, GEMM_SMEM_BYTES);
    cudaFuncSetAttribute(tc_gemm_loss,  cudaFuncAttributeMaxDynamicSharedMemorySize, GEMM_SMEM_BYTES);

    void* p;
    cudaGetSymbolAddress(&p, g_x);      float* px    = (float*)p;
    cudaGetSymbolAddress(&p, g_xb);     bf16*  pxb   = (bf16*)p;
    cudaGetSymbolAddress(&p, g_qkvb);   bf16*  pqkvb = (bf16*)p;
    cudaGetSymbolAddress(&p, g_ctxb);   bf16*  pctxb = (bf16*)p;
    cudaGetSymbolAddress(&p, g_proj);   float* pproj = (float*)p;
    cudaGetSymbolAddress(&p, g_ffnb);   bf16*  pffnb = (bf16*)p;
    cudaGetSymbolAddress(&p, g_bqkv);   float* pbqkv = (float*)p;
    cudaGetSymbolAddress(&p, g_WqkvT);  bf16*  pWqkvT= (bf16*)p;
    cudaGetSymbolAddress(&p, g_WoT);    bf16*  pWoT  = (bf16*)p;
    cudaGetSymbolAddress(&p, g_WiT);    bf16*  pWiT  = (bf16*)p;
    cudaGetSymbolAddress(&p, g_WdT);    bf16*  pWdT  = (bf16*)p;
    cudaGetSymbolAddress(&p, g_WcT);    bf16*  pWcT  = (bf16*)p;

    // Batched weight transposes (7 launches)
    const size_t HH = (size_t)Hc * Hc;
    run_tr_b(Wq, pWqkvT,                    Hc, Hc, HH, (size_t)QKVN*Hc, Lc);
    run_tr_b(Wk, pWqkvT + HH,               Hc, Hc, HH, (size_t)QKVN*Hc, Lc);
    run_tr_b(Wv, pWqkvT + 2*HH,             Hc, Hc, HH, (size_t)QKVN*Hc, Lc);
    run_tr_b(Wo, pWoT,                      Hc, Hc, HH, HH, Lc);
    run_tr_b(Wi, pWiT,  Hc, FFc, (size_t)Hc*FFc, (size_t)FFc*Hc, Lc);
    run_tr_b(Wd, pWdT,  FFc, Hc, (size_t)FFc*Hc, (size_t)Hc*FFc, Lc);
    run_tr_b(Wc, pWcT,  Hc, Vc,  0, 0, 1);

    build_qkv_bias<<<(Lc*QKVN + 255)/256, 256>>>(bq, bk, bv);
    sep_kernel<<<1, 32>>>(ids);
    embed_ln_kernel<<<Mc, 256>>>(ids, word_emb, pos_emb, type_emb, eg, eb);

    for (int l = 0; l < Lc; l++) {
        run_gemm_t<0,1>(pxb, pWqkvT + (size_t)l*QKVN*Hc, pbqkv + (size_t)l*QKVN,
                        pqkvb, Mc, QKVN, Hc);
        attn3_kernel<<<dim3(Sc/64, NHc, Bc), 256, AT_SMEM>>>(pqkvb, pctxb);
        run_gemm64_t<0,0>(pctxb, pWoT + (size_t)l*HH, bo + (size_t)l*Hc, pproj, Mc, Hc, Hc);
        add_ln_kernel<<<Mc, 256>>>(px, pxb, pproj, l1g + (size_t)l*Hc, l1b + (size_t)l*Hc);
        run_gemm_t<1,1>(pxb, pWiT + (size_t)l*FFc*Hc, bi + (size_t)l*FFc, pffnb, Mc, FFc, Hc);
        run_gemm64_t<0,0>(pffnb, pWdT + (size_t)l*Hc*FFc, bd + (size_t)l*Hc, pproj, Mc, Hc, FFc);
        add_ln_kernel<<<Mc, 256>>>(px, pxb, pproj, l2g + (size_t)l*Hc, l2b + (size_t)l*Hc);
    }

    // classifier + fused loss
    {
        dim3 grid(NTILES, Mc / 128);
        tc_gemm_loss<<<grid, 256, GEMM_SMEM_BYTES>>>(pxb, pWcT, bc, labels, Mc, Vc, Hc);
    }
    loss_merge<<<(Mc * 32 + 255) / 256, 256>>>(labels);
    loss_reduce_kernel<<<1, 1024>>>((float*)d_out);
}